// round 11
// baseline (speedup 1.0000x reference)
#include <cuda_runtime.h>
#include <cuda_fp16.h>
#include <cstdint>

#define NSVC 50000
#define NNODE 20000
#define NPOD 100000
#define FD 128
#define OUTD 64
#define ESVC_MAX 1600000
#define EPN_MAX  100000
#define ENP_MAX  100000

// ---- degree/norm array layout ----
#define DEG_SVC_SRC 0
#define DEG_SVC_DST (NSVC)
#define DEG_PN_SRC  (2*NSVC)
#define DEG_PN_DST  (2*NSVC + NPOD)
#define DEG_NP_SRC  (2*NSVC + NPOD + NNODE)
#define DEG_NP_DST  (2*NSVC + NPOD + 2*NNODE)
#define DEG_TOTAL   (2*NSVC + 2*NPOD + 2*NNODE)

#define OFF_SVC  0
#define OFF_NODE (NSVC)
#define OFF_POD  (NSVC + NNODE)
#define OFF_TOTAL (NSVC + NNODE + NPOD)

#define AGG_SVC_OFF  ((size_t)0)
#define AGG_NODE_OFF ((size_t)NSVC * FD)
#define AGG_POD_OFF  ((size_t)(NSVC + NNODE) * FD)
#define AGG_TOTAL    ((size_t)(NSVC + NNODE + NPOD) * FD)

// fp16 feature buffer layout (rows in input-tensor order)
#define XH_SVC_OFF  ((size_t)0)
#define XH_POD_OFF  ((size_t)NSVC * FD)
#define XH_NODE_OFF ((size_t)(NSVC + NPOD) * FD)
#define XH_TOTAL    ((size_t)(NSVC + NPOD + NNODE) * FD)

// scan block mapping (1024-wide blocks)
#define NB_SVC  49
#define NB_NODE 20
#define NB_POD  98
#define NB_ALL  167

// gemm block mapping (128 rows/block)
#define GB_SVC  391
#define GB_NODE 157
#define GB_POD  782
#define GB_ALL  1330

__device__ float g_agg[AGG_TOTAL];
__device__ __half g_xh[XH_TOTAL];
__device__ int   g_deg[DEG_TOTAL];
__device__ float g_nrm[DEG_TOTAL];
__device__ int   g_off[OFF_TOTAL];
__device__ int   g_fill[OFF_TOTAL];
__device__ int   g_part[3 * 128];
__device__ int   g_eidx_svc[ESVC_MAX];
__device__ int   g_eidx_pn[EPN_MAX];
__device__ int   g_eidx_np[ENP_MAX];

// fp16 weights (transposed [n][k]); only hi — A-side carries the residual
__device__ __half g_w1h[3][128 * 128];
__device__ __half g_w2h[3][64 * 128];

// ============================================================
// K1: zero counters + weight conversion + x fp16 conversion
// ============================================================
__device__ __forceinline__ void conv8(const float* src, __half* dst, size_t n8,
                                      size_t tid0, size_t stride) {
    const float4* s4 = (const float4*)src;
    uint2* d2 = (uint2*)dst;  // 4 halves per uint2... use uint4 for 8 halves
    uint4* d4 = (uint4*)dst;
    for (size_t i = tid0; i < n8; i += stride) {
        float4 a = s4[i * 2];
        float4 b = s4[i * 2 + 1];
        __half2 h0 = __floats2half2_rn(a.x, a.y);
        __half2 h1 = __floats2half2_rn(a.z, a.w);
        __half2 h2 = __floats2half2_rn(b.x, b.y);
        __half2 h3 = __floats2half2_rn(b.z, b.w);
        d4[i] = make_uint4(*(uint32_t*)&h0, *(uint32_t*)&h1,
                           *(uint32_t*)&h2, *(uint32_t*)&h3);
    }
}

__global__ void prep0(const float* __restrict__ W1_0, const float* __restrict__ W2_0,
                      const float* __restrict__ W1_1, const float* __restrict__ W2_1,
                      const float* __restrict__ W1_2, const float* __restrict__ W2_2,
                      const float* __restrict__ x_svc, const float* __restrict__ x_pod,
                      const float* __restrict__ x_node) {
    size_t tid0 = blockIdx.x * blockDim.x + threadIdx.x;
    size_t stride = (size_t)gridDim.x * blockDim.x;
    for (size_t i = tid0; i < DEG_TOTAL; i += stride) g_deg[i] = 0;
    for (size_t i = tid0; i < OFF_TOTAL; i += stride) g_fill[i] = 0;

    // x -> fp16
    conv8(x_svc,  g_xh + XH_SVC_OFF,  (size_t)NSVC * FD / 8,  tid0, stride);
    conv8(x_pod,  g_xh + XH_POD_OFF,  (size_t)NPOD * FD / 8,  tid0, stride);
    conv8(x_node, g_xh + XH_NODE_OFF, (size_t)NNODE * FD / 8, tid0, stride);

    size_t idx = tid0;
    if (idx < 73728) {
        int t = (int)(idx / 24576);
        int r = (int)(idx % 24576);
        const float* W1 = (t == 0) ? W1_0 : (t == 1) ? W1_1 : W1_2;
        const float* W2 = (t == 0) ? W2_0 : (t == 1) ? W2_1 : W2_2;
        if (r < 16384) {
            int n = r >> 7, k = r & 127;
            g_w1h[t][n * 128 + k] = __float2half_rn(__ldg(W1 + k * 128 + n));
        } else {
            int q = r - 16384;
            int n = q >> 7, k = q & 127;
            g_w2h[t][n * 128 + k] = __float2half_rn(__ldg(W2 + k * 64 + n));
        }
    }
}

// ============================================================
// K2: degree counting, all three edge types in one grid
// ============================================================
__global__ void deg_all(const int* __restrict__ svc_src, const int* __restrict__ svc_dst,
                        const int* __restrict__ pn_src,  const int* __restrict__ pn_dst,
                        const int* __restrict__ np_src,  const int* __restrict__ np_dst,
                        int E_svc, int E_pn, int E_np) {
    int i = blockIdx.x * blockDim.x + threadIdx.x;
    if (i < E_svc) {
        atomicAdd(&g_deg[DEG_SVC_SRC + svc_src[i]], 1);
        atomicAdd(&g_deg[DEG_SVC_DST + svc_dst[i]], 1);
    } else if (i < E_svc + E_pn) {
        int e = i - E_svc;
        atomicAdd(&g_deg[DEG_PN_SRC + pn_src[e]], 1);
        atomicAdd(&g_deg[DEG_PN_DST + pn_dst[e]], 1);
    } else if (i < E_svc + E_pn + E_np) {
        int e = i - E_svc - E_pn;
        atomicAdd(&g_deg[DEG_NP_SRC + np_src[e]], 1);
        atomicAdd(&g_deg[DEG_NP_DST + np_dst[e]], 1);
    }
}

// ============================================================
// K3: per-type block scan (stage 1) + nrm computation
// ============================================================
__device__ __forceinline__ void scan_map(int b, int& t, int& lb,
                                         const int*& deg, int*& out, int& n) {
    if (b < NB_SVC)             { t = 0; lb = b;                    deg = g_deg + DEG_SVC_DST; out = g_off + OFF_SVC;  n = NSVC; }
    else if (b < NB_SVC+NB_NODE){ t = 1; lb = b - NB_SVC;           deg = g_deg + DEG_PN_DST;  out = g_off + OFF_NODE; n = NNODE; }
    else                        { t = 2; lb = b - NB_SVC - NB_NODE; deg = g_deg + DEG_NP_DST;  out = g_off + OFF_POD;  n = NPOD; }
}

__global__ void scan1_all() {
    {
        int tid0 = blockIdx.x * blockDim.x + threadIdx.x;
        int stride = gridDim.x * blockDim.x;
        for (int i = tid0; i < DEG_TOTAL; i += stride) {
            int d = g_deg[i];
            g_nrm[i] = rsqrtf((float)(d > 1 ? d : 1));
        }
    }
    __shared__ int s[1024];
    int t, lb, n;
    const int* deg;
    int* out;
    scan_map(blockIdx.x, t, lb, deg, out, n);
    int tt = threadIdx.x;
    int i = lb * 1024 + tt;
    int v = (i < n) ? deg[i] : 0;
    s[tt] = v;
    __syncthreads();
    #pragma unroll
    for (int d = 1; d < 1024; d <<= 1) {
        int tv = (tt >= d) ? s[tt - d] : 0;
        __syncthreads();
        s[tt] += tv;
        __syncthreads();
    }
    if (i < n) out[i] = s[tt] - v;
    if (tt == 1023) g_part[t * 128 + lb] = s[tt];
}

// ============================================================
// K4: merged scan2+scan3
// ============================================================
__global__ void scan23_all() {
    __shared__ int p[128];
    int t, lb, n;
    const int* deg;
    int* out;
    scan_map(blockIdx.x, t, lb, deg, out, n);
    int tt = threadIdx.x;
    if (tt < 128) p[tt] = (tt < lb) ? g_part[t * 128 + tt] : 0;
    __syncthreads();
    #pragma unroll
    for (int d = 64; d > 0; d >>= 1) {
        if (tt < d) p[tt] += p[tt + d];
        __syncthreads();
    }
    int carry = p[0];
    int i = lb * 1024 + tt;
    if (i < n) out[i] += carry;
}

// ============================================================
// K5: fill CSR edge lists, all types
// ============================================================
__global__ void fill_all(const int* __restrict__ svc_src, const int* __restrict__ svc_dst,
                         const int* __restrict__ pn_src,  const int* __restrict__ pn_dst,
                         const int* __restrict__ np_src,  const int* __restrict__ np_dst,
                         int E_svc, int E_pn, int E_np) {
    int i = blockIdx.x * blockDim.x + threadIdx.x;
    if (i < E_svc) {
        int d = svc_dst[i];
        int p = atomicAdd(&g_fill[OFF_SVC + d], 1);
        g_eidx_svc[g_off[OFF_SVC + d] + p] = svc_src[i];
    } else if (i < E_svc + E_pn) {
        int e = i - E_svc;
        int d = pn_dst[e];
        int p = atomicAdd(&g_fill[OFF_NODE + d], 1);
        g_eidx_pn[g_off[OFF_NODE + d] + p] = pn_src[e];
    } else if (i < E_svc + E_pn + E_np) {
        int e = i - E_svc - E_pn;
        int d = np_dst[e];
        int p = atomicAdd(&g_fill[OFF_POD + d], 1);
        g_eidx_np[g_off[OFF_POD + d] + p] = np_src[e];
    }
}

// ============================================================
// K6: warp-per-dst-row gather (fp16 features, fp32 accumulate)
// ============================================================
__global__ void gather_all() {
    int w = (blockIdx.x * blockDim.x + threadIdx.x) >> 5;
    int lane = threadIdx.x & 31;
    if (w >= OFF_TOTAL) return;

    const __half* x;
    const int* eidx;
    const int* off;
    const int* cnt;
    const float* nsrc;
    const float* ndst;
    float* agg;
    int local;
    if (w < NSVC) {
        local = w;
        x = g_xh + XH_SVC_OFF; eidx = g_eidx_svc; off = g_off + OFF_SVC;
        cnt = g_deg + DEG_SVC_DST; nsrc = g_nrm + DEG_SVC_SRC; ndst = g_nrm + DEG_SVC_DST;
        agg = g_agg + AGG_SVC_OFF;
    } else if (w < NSVC + NNODE) {
        local = w - NSVC;
        x = g_xh + XH_POD_OFF; eidx = g_eidx_pn; off = g_off + OFF_NODE;
        cnt = g_deg + DEG_PN_DST; nsrc = g_nrm + DEG_PN_SRC; ndst = g_nrm + DEG_PN_DST;
        agg = g_agg + AGG_NODE_OFF;
    } else {
        local = w - NSVC - NNODE;
        x = g_xh + XH_NODE_OFF; eidx = g_eidx_np; off = g_off + OFF_POD;
        cnt = g_deg + DEG_NP_DST; nsrc = g_nrm + DEG_NP_SRC; ndst = g_nrm + DEG_NP_DST;
        agg = g_agg + AGG_POD_OFF;
    }

    int beg = off[local];
    int end = beg + cnt[local];
    const uint2* x2 = reinterpret_cast<const uint2*>(x);  // 4 halves per uint2, 32/row

    float4 acc = make_float4(0.f, 0.f, 0.f, 0.f);
    int e = beg;
    for (; e + 4 <= end; e += 4) {
        int s0 = __ldg(eidx + e + 0);
        int s1 = __ldg(eidx + e + 1);
        int s2 = __ldg(eidx + e + 2);
        int s3 = __ldg(eidx + e + 3);
        float n0 = __ldg(nsrc + s0);
        float n1 = __ldg(nsrc + s1);
        float n2 = __ldg(nsrc + s2);
        float n3 = __ldg(nsrc + s3);
        uint2 u0 = x2[(size_t)s0 * 32 + lane];
        uint2 u1 = x2[(size_t)s1 * 32 + lane];
        uint2 u2 = x2[(size_t)s2 * 32 + lane];
        uint2 u3 = x2[(size_t)s3 * 32 + lane];
        float2 a0 = __half22float2(*(__half2*)&u0.x), b0 = __half22float2(*(__half2*)&u0.y);
        float2 a1 = __half22float2(*(__half2*)&u1.x), b1 = __half22float2(*(__half2*)&u1.y);
        float2 a2 = __half22float2(*(__half2*)&u2.x), b2 = __half22float2(*(__half2*)&u2.y);
        float2 a3 = __half22float2(*(__half2*)&u3.x), b3 = __half22float2(*(__half2*)&u3.y);
        acc.x += a0.x * n0; acc.y += a0.y * n0; acc.z += b0.x * n0; acc.w += b0.y * n0;
        acc.x += a1.x * n1; acc.y += a1.y * n1; acc.z += b1.x * n1; acc.w += b1.y * n1;
        acc.x += a2.x * n2; acc.y += a2.y * n2; acc.z += b2.x * n2; acc.w += b2.y * n2;
        acc.x += a3.x * n3; acc.y += a3.y * n3; acc.z += b3.x * n3; acc.w += b3.y * n3;
    }
    for (; e < end; e++) {
        int s0 = __ldg(eidx + e);
        float n0 = __ldg(nsrc + s0);
        uint2 u0 = x2[(size_t)s0 * 32 + lane];
        float2 a0 = __half22float2(*(__half2*)&u0.x), b0 = __half22float2(*(__half2*)&u0.y);
        acc.x += a0.x * n0; acc.y += a0.y * n0; acc.z += b0.x * n0; acc.w += b0.y * n0;
    }
    float nd = ndst[local];
    // lane covers cols [lane*4, lane*4+4)
    reinterpret_cast<float4*>(agg)[(size_t)local * 32 + lane] =
        make_float4(acc.x * nd, acc.y * nd, acc.z * nd, acc.w * nd);
}

// ============================================================
// K7: fused mma.sync fp16 2-product GEMM (unchanged from R10)
// ============================================================
#define SROWB 272
#define SM_A_HI 0
#define SM_A_LO 34816
#define SM_W1H  69632
#define SM_W2H  104448
#define SM_B1   121856
#define SM_B2   122368
#define SM_TOTAL 122624

__device__ __forceinline__ uint32_t pack_h2(__half a, __half b) {
    return (uint32_t)__half_as_ushort(a) | ((uint32_t)__half_as_ushort(b) << 16);
}
__device__ __forceinline__ void split_h(float v, __half& hi, __half& lo) {
    hi = __float2half_rn(v);
    lo = __float2half_rn(v - __half2float(hi));
}
__device__ __forceinline__ void mma_f16(float* c, uint32_t a0, uint32_t a1,
                                        uint32_t a2, uint32_t a3,
                                        uint32_t b0, uint32_t b1) {
    asm volatile(
        "mma.sync.aligned.m16n8k16.row.col.f32.f16.f16.f32 "
        "{%0,%1,%2,%3}, {%4,%5,%6,%7}, {%8,%9}, {%0,%1,%2,%3};"
        : "+f"(c[0]), "+f"(c[1]), "+f"(c[2]), "+f"(c[3])
        : "r"(a0), "r"(a1), "r"(a2), "r"(a3), "r"(b0), "r"(b1));
}
__device__ __forceinline__ uint32_t lds_u32(const char* base, int row, int col) {
    return *(const uint32_t*)(base + row * SROWB + col * 2);
}

__global__ void __launch_bounds__(256, 1)
gemm_all(const float* __restrict__ b_call, const float* __restrict__ b_lin_svc,
         const float* __restrict__ b_in,   const float* __restrict__ b_lin_node,
         const float* __restrict__ b_ni,   const float* __restrict__ b_lin_pod,
         float* __restrict__ out_base) {
    extern __shared__ char sm[];
    int tid = threadIdx.x;
    int wid = tid >> 5;
    int lane = tid & 31;
    int g = lane >> 2;
    int tig = lane & 3;

    int b = blockIdx.x;
    int t, lb, M;
    const float* agg;
    const float* b1;
    const float* b2;
    float* out;
    if (b < GB_SVC) {
        t = 0; lb = b; M = NSVC;
        agg = g_agg + AGG_SVC_OFF; b1 = b_call; b2 = b_lin_svc;
        out = out_base;
    } else if (b < GB_SVC + GB_NODE) {
        t = 1; lb = b - GB_SVC; M = NNODE;
        agg = g_agg + AGG_NODE_OFF; b1 = b_in; b2 = b_lin_node;
        out = out_base + (size_t)NSVC * OUTD;
    } else {
        t = 2; lb = b - GB_SVC - GB_NODE; M = NPOD;
        agg = g_agg + AGG_POD_OFF; b1 = b_ni; b2 = b_lin_pod;
        out = out_base + (size_t)(NSVC + NNODE) * OUTD;
    }

    // ---- stage weights ----
    {
        const uint4* s1 = (const uint4*)g_w1h[t];
        #pragma unroll
        for (int i = 0; i < 8; i++) {
            int idx = i * 256 + tid;
            int row = idx >> 4, gq = idx & 15;
            *(uint4*)(sm + SM_W1H + row * SROWB + gq * 16) = s1[idx];
        }
        const uint4* s2 = (const uint4*)g_w2h[t];
        #pragma unroll
        for (int i = 0; i < 4; i++) {
            int idx = i * 256 + tid;
            int row = idx >> 4, gq = idx & 15;
            *(uint4*)(sm + SM_W2H + row * SROWB + gq * 16) = s2[idx];
        }
    }
    if (tid < 128) ((float*)(sm + SM_B1))[tid] = b1[tid];
    else if (tid < 192) ((float*)(sm + SM_B2))[tid - 128] = b2[tid - 128];

    // ---- load + split A tile (fp16 hi/lo) ----
    {
        int row = tid >> 1;
        int half = (tid & 1) * 64;
        int grow = lb * 128 + row;
        const float4* av = (const float4*)agg + (size_t)grow * 32 + (half >> 2);
        #pragma unroll
        for (int j = 0; j < 16; j++) {
            float4 v = (grow < M) ? av[j] : make_float4(0.f, 0.f, 0.f, 0.f);
            __half h0, h1, h2, h3, l0, l1, l2, l3;
            split_h(v.x, h0, l0); split_h(v.y, h1, l1);
            split_h(v.z, h2, l2); split_h(v.w, h3, l3);
            int col = half + j * 4;
            *(uint2*)(sm + SM_A_HI + row * SROWB + col * 2) =
                make_uint2(pack_h2(h0, h1), pack_h2(h2, h3));
            *(uint2*)(sm + SM_A_LO + row * SROWB + col * 2) =
                make_uint2(pack_h2(l0, l1), pack_h2(l2, l3));
        }
    }
    __syncthreads();

    int mtb = (wid & 3) * 2;
    int nb1 = (wid >> 2) * 64;

    // ---- GEMM1 ----
    float acc[2][8][4];
    #pragma unroll
    for (int mt = 0; mt < 2; mt++)
        #pragma unroll
        for (int nt = 0; nt < 8; nt++)
            #pragma unroll
            for (int q = 0; q < 4; q++) acc[mt][nt][q] = 0.f;

    #pragma unroll
    for (int kc = 0; kc < 8; kc++) {
        int k0 = kc * 16 + tig * 2;
        uint32_t ah[2][4], al[2][4];
        #pragma unroll
        for (int mt = 0; mt < 2; mt++) {
            int r = (mtb + mt) * 16 + g;
            ah[mt][0] = lds_u32(sm + SM_A_HI, r,     k0);
            ah[mt][1] = lds_u32(sm + SM_A_HI, r + 8, k0);
            ah[mt][2] = lds_u32(sm + SM_A_HI, r,     k0 + 8);
            ah[mt][3] = lds_u32(sm + SM_A_HI, r + 8, k0 + 8);
            al[mt][0] = lds_u32(sm + SM_A_LO, r,     k0);
            al[mt][1] = lds_u32(sm + SM_A_LO, r + 8, k0);
            al[mt][2] = lds_u32(sm + SM_A_LO, r,     k0 + 8);
            al[mt][3] = lds_u32(sm + SM_A_LO, r + 8, k0 + 8);
        }
        #pragma unroll
        for (int nt = 0; nt < 8; nt++) {
            int n = nb1 + nt * 8 + g;
            uint32_t bh0 = lds_u32(sm + SM_W1H, n, k0);
            uint32_t bh1 = lds_u32(sm + SM_W1H, n, k0 + 8);
            #pragma unroll
            for (int mt = 0; mt < 2; mt++) {
                mma_f16(acc[mt][nt], ah[mt][0], ah[mt][1], ah[mt][2], ah[mt][3], bh0, bh1);
                mma_f16(acc[mt][nt], al[mt][0], al[mt][1], al[mt][2], al[mt][3], bh0, bh1);
            }
        }
    }
    __syncthreads();

    // ---- epilogue1: bias + leaky + fp16 re-split ----
    {
        const float* b1s = (const float*)(sm + SM_B1);
        #pragma unroll
        for (int mt = 0; mt < 2; mt++) {
            #pragma unroll
            for (int nt = 0; nt < 8; nt++) {
                int row = (mtb + mt) * 16 + g;
                int col = nb1 + nt * 8 + tig * 2;
                float bb0 = b1s[col], bb1 = b1s[col + 1];
                float v0 = acc[mt][nt][0] + bb0;
                float v1 = acc[mt][nt][1] + bb1;
                float v2 = acc[mt][nt][2] + bb0;
                float v3 = acc[mt][nt][3] + bb1;
                v0 = v0 > 0.f ? v0 : 0.01f * v0;
                v1 = v1 > 0.f ? v1 : 0.01f * v1;
                v2 = v2 > 0.f ? v2 : 0.01f * v2;
                v3 = v3 > 0.f ? v3 : 0.01f * v3;
                __half h0, h1, h2, h3, l0, l1, l2, l3;
                split_h(v0, h0, l0); split_h(v1, h1, l1);
                split_h(v2, h2, l2); split_h(v3, h3, l3);
                *(uint32_t*)(sm + SM_A_HI + row * SROWB + col * 2) = pack_h2(h0, h1);
                *(uint32_t*)(sm + SM_A_LO + row * SROWB + col * 2) = pack_h2(l0, l1);
                *(uint32_t*)(sm + SM_A_HI + (row + 8) * SROWB + col * 2) = pack_h2(h2, h3);
                *(uint32_t*)(sm + SM_A_LO + (row + 8) * SROWB + col * 2) = pack_h2(l2, l3);
            }
        }
    }
    __syncthreads();

    // ---- GEMM2 ----
    int nb2 = (wid >> 2) * 32;
    float acc2[2][4][4];
    #pragma unroll
    for (int mt = 0; mt < 2; mt++)
        #pragma unroll
        for (int nt = 0; nt < 4; nt++)
            #pragma unroll
            for (int q = 0; q < 4; q++) acc2[mt][nt][q] = 0.f;

    #pragma unroll
    for (int kc = 0; kc < 8; kc++) {
        int k0 = kc * 16 + tig * 2;
        uint32_t ah[2][4], al[2][4];
        #pragma unroll
        for (int mt = 0; mt < 2; mt++) {
            int r = (mtb + mt) * 16 + g;
            ah[mt][0] = lds_u32(sm + SM_A_HI, r,     k0);
            ah[mt][1] = lds_u32(sm + SM_A_HI, r + 8, k0);
            ah[mt][2] = lds_u32(sm + SM_A_HI, r,     k0 + 8);
            ah[mt][3] = lds_u32(sm + SM_A_HI, r + 8, k0 + 8);
            al[mt][0] = lds_u32(sm + SM_A_LO, r,     k0);
            al[mt][1] = lds_u32(sm + SM_A_LO, r + 8, k0);
            al[mt][2] = lds_u32(sm + SM_A_LO, r,     k0 + 8);
            al[mt][3] = lds_u32(sm + SM_A_LO, r + 8, k0 + 8);
        }
        #pragma unroll
        for (int nt = 0; nt < 4; nt++) {
            int n = nb2 + nt * 8 + g;
            uint32_t bh0 = lds_u32(sm + SM_W2H, n, k0);
            uint32_t bh1 = lds_u32(sm + SM_W2H, n, k0 + 8);
            #pragma unroll
            for (int mt = 0; mt < 2; mt++) {
                mma_f16(acc2[mt][nt], ah[mt][0], ah[mt][1], ah[mt][2], ah[mt][3], bh0, bh1);
                mma_f16(acc2[mt][nt], al[mt][0], al[mt][1], al[mt][2], al[mt][3], bh0, bh1);
            }
        }
    }

    // ---- epilogue2 ----
    {
        const float* b2s = (const float*)(sm + SM_B2);
        #pragma unroll
        for (int mt = 0; mt < 2; mt++) {
            #pragma unroll
            for (int nt = 0; nt < 4; nt++) {
                int row = lb * 128 + (mtb + mt) * 16 + g;
                int col = nb2 + nt * 8 + tig * 2;
                float bb0 = b2s[col], bb1 = b2s[col + 1];
                if (row < M)
                    *(float2*)(out + (size_t)row * 64 + col) =
                        make_float2(acc2[mt][nt][0] + bb0, acc2[mt][nt][1] + bb1);
                if (row + 8 < M)
                    *(float2*)(out + (size_t)(row + 8) * 64 + col) =
                        make_float2(acc2[mt][nt][2] + bb0, acc2[mt][nt][3] + bb1);
            }
        }
    }
}

// ============================================================
// launch — 7 kernels total
// ============================================================
extern "C" void kernel_launch(void* const* d_in, const int* in_sizes, int n_in,
                              void* d_out, int out_size) {
    const float* x_svc  = (const float*)d_in[0];
    const float* x_pod  = (const float*)d_in[1];
    const float* x_node = (const float*)d_in[2];
    const int* svc_src = (const int*)d_in[3];
    const int* svc_dst = (const int*)d_in[4];
    const int* pn_src  = (const int*)d_in[5];
    const int* pn_dst  = (const int*)d_in[6];
    const int* np_src  = (const int*)d_in[7];
    const int* np_dst  = (const int*)d_in[8];
    const float* W_call = (const float*)d_in[9];
    const float* b_call = (const float*)d_in[10];
    const float* W_in   = (const float*)d_in[11];
    const float* b_in   = (const float*)d_in[12];
    const float* W_ni   = (const float*)d_in[13];
    const float* b_ni   = (const float*)d_in[14];
    const float* W_lin_svc  = (const float*)d_in[15];
    const float* b_lin_svc  = (const float*)d_in[16];
    const float* W_lin_node = (const float*)d_in[17];
    const float* b_lin_node = (const float*)d_in[18];
    const float* W_lin_pod  = (const float*)d_in[19];
    const float* b_lin_pod  = (const float*)d_in[20];
    float* out = (float*)d_out;

    int E_svc = in_sizes[3];
    int E_pn  = in_sizes[5];
    int E_np  = in_sizes[7];
    int E_tot = E_svc + E_pn + E_np;

    cudaFuncSetAttribute(gemm_all, cudaFuncAttributeMaxDynamicSharedMemorySize, SM_TOTAL);

    prep0<<<1024, 256>>>(W_call, W_lin_svc, W_in, W_lin_node, W_ni, W_lin_pod,
                         x_svc, x_pod, x_node);

    deg_all<<<(E_tot + 255) / 256, 256>>>(svc_src, svc_dst, pn_src, pn_dst,
                                          np_src, np_dst, E_svc, E_pn, E_np);

    scan1_all<<<NB_ALL, 1024>>>();
    scan23_all<<<NB_ALL, 1024>>>();

    fill_all<<<(E_tot + 255) / 256, 256>>>(svc_src, svc_dst, pn_src, pn_dst,
                                           np_src, np_dst, E_svc, E_pn, E_np);

    gather_all<<<(OFF_TOTAL + 7) / 8, 256>>>();

    gemm_all<<<GB_ALL, 256, SM_TOTAL>>>(b_call, b_lin_svc, b_in, b_lin_node,
                                        b_ni, b_lin_pod, out);
}

// round 12
// speedup vs baseline: 1.2023x; 1.2023x over previous
#include <cuda_runtime.h>
#include <cuda_fp16.h>
#include <cstdint>

#define NSVC 50000
#define NNODE 20000
#define NPOD 100000
#define FD 128
#define OUTD 64
#define ESVC_MAX 1600000
#define EPN_MAX  100000
#define ENP_MAX  100000

// ---- degree/norm array layout ----
#define DEG_SVC_SRC 0
#define DEG_SVC_DST (NSVC)
#define DEG_PN_SRC  (2*NSVC)
#define DEG_PN_DST  (2*NSVC + NPOD)
#define DEG_NP_SRC  (2*NSVC + NPOD + NNODE)
#define DEG_NP_DST  (2*NSVC + NPOD + 2*NNODE)
#define DEG_TOTAL   (2*NSVC + 2*NPOD + 2*NNODE)

#define OFF_SVC  0
#define OFF_NODE (NSVC)
#define OFF_POD  (NSVC + NNODE)
#define OFF_TOTAL (NSVC + NNODE + NPOD)

#define AGG_SVC_OFF  ((size_t)0)
#define AGG_NODE_OFF ((size_t)NSVC * FD)
#define AGG_POD_OFF  ((size_t)(NSVC + NNODE) * FD)
#define AGG_TOTAL    ((size_t)(NSVC + NNODE + NPOD) * FD)

// scan block mapping (1024-wide blocks)
#define NB_SVC  49
#define NB_NODE 20
#define NB_POD  98
#define NB_ALL  167

// gemm block mapping (128 rows/block)
#define GB_SVC  391
#define GB_NODE 157
#define GB_POD  782
#define GB_ALL  1330

__device__ float g_agg[AGG_TOTAL];
__device__ int   g_deg[DEG_TOTAL];
__device__ float g_nrm[DEG_TOTAL];
__device__ int   g_off[OFF_TOTAL];
__device__ int   g_fill[OFF_TOTAL];
__device__ int   g_part[3 * 128];
__device__ int   g_eidx_svc[ESVC_MAX];
__device__ int   g_eidx_pn[EPN_MAX];
__device__ int   g_eidx_np[ENP_MAX];

// fp16 weights (transposed [n][k])
__device__ __half g_w1h[3][128 * 128];
__device__ __half g_w2h[3][64 * 128];

// ============================================================
// K1: zero counters + weight conversion (fused) — R10 form
// ============================================================
__global__ void prep0(const float* __restrict__ W1_0, const float* __restrict__ W2_0,
                      const float* __restrict__ W1_1, const float* __restrict__ W2_1,
                      const float* __restrict__ W1_2, const float* __restrict__ W2_2) {
    int tid0 = blockIdx.x * blockDim.x + threadIdx.x;
    int stride = gridDim.x * blockDim.x;
    for (int i = tid0; i < DEG_TOTAL; i += stride) g_deg[i] = 0;
    for (int i = tid0; i < OFF_TOTAL; i += stride) g_fill[i] = 0;

    int idx = tid0;
    if (idx < 73728) {
        int t = idx / 24576;
        int r = idx % 24576;
        const float* W1 = (t == 0) ? W1_0 : (t == 1) ? W1_1 : W1_2;
        const float* W2 = (t == 0) ? W2_0 : (t == 1) ? W2_1 : W2_2;
        if (r < 16384) {
            int n = r >> 7, k = r & 127;
            g_w1h[t][n * 128 + k] = __float2half_rn(__ldg(W1 + k * 128 + n));
        } else {
            int q = r - 16384;
            int n = q >> 7, k = q & 127;
            g_w2h[t][n * 128 + k] = __float2half_rn(__ldg(W2 + k * 64 + n));
        }
    }
}

// ============================================================
// K2: degree counting, all three edge types in one grid
// ============================================================
__global__ void deg_all(const int* __restrict__ svc_src, const int* __restrict__ svc_dst,
                        const int* __restrict__ pn_src,  const int* __restrict__ pn_dst,
                        const int* __restrict__ np_src,  const int* __restrict__ np_dst,
                        int E_svc, int E_pn, int E_np) {
    int i = blockIdx.x * blockDim.x + threadIdx.x;
    if (i < E_svc) {
        atomicAdd(&g_deg[DEG_SVC_SRC + svc_src[i]], 1);
        atomicAdd(&g_deg[DEG_SVC_DST + svc_dst[i]], 1);
    } else if (i < E_svc + E_pn) {
        int e = i - E_svc;
        atomicAdd(&g_deg[DEG_PN_SRC + pn_src[e]], 1);
        atomicAdd(&g_deg[DEG_PN_DST + pn_dst[e]], 1);
    } else if (i < E_svc + E_pn + E_np) {
        int e = i - E_svc - E_pn;
        atomicAdd(&g_deg[DEG_NP_SRC + np_src[e]], 1);
        atomicAdd(&g_deg[DEG_NP_DST + np_dst[e]], 1);
    }
}

// ============================================================
// K3: per-type block scan (stage 1) + nrm computation
// ============================================================
__device__ __forceinline__ void scan_map(int b, int& t, int& lb,
                                         const int*& deg, int*& out, int& n) {
    if (b < NB_SVC)             { t = 0; lb = b;                    deg = g_deg + DEG_SVC_DST; out = g_off + OFF_SVC;  n = NSVC; }
    else if (b < NB_SVC+NB_NODE){ t = 1; lb = b - NB_SVC;           deg = g_deg + DEG_PN_DST;  out = g_off + OFF_NODE; n = NNODE; }
    else                        { t = 2; lb = b - NB_SVC - NB_NODE; deg = g_deg + DEG_NP_DST;  out = g_off + OFF_POD;  n = NPOD; }
}

__global__ void scan1_all() {
    {
        int tid0 = blockIdx.x * blockDim.x + threadIdx.x;
        int stride = gridDim.x * blockDim.x;
        for (int i = tid0; i < DEG_TOTAL; i += stride) {
            int d = g_deg[i];
            g_nrm[i] = rsqrtf((float)(d > 1 ? d : 1));
        }
    }
    __shared__ int s[1024];
    int t, lb, n;
    const int* deg;
    int* out;
    scan_map(blockIdx.x, t, lb, deg, out, n);
    int tt = threadIdx.x;
    int i = lb * 1024 + tt;
    int v = (i < n) ? deg[i] : 0;
    s[tt] = v;
    __syncthreads();
    #pragma unroll
    for (int d = 1; d < 1024; d <<= 1) {
        int tv = (tt >= d) ? s[tt - d] : 0;
        __syncthreads();
        s[tt] += tv;
        __syncthreads();
    }
    if (i < n) out[i] = s[tt] - v;
    if (tt == 1023) g_part[t * 128 + lb] = s[tt];
}

// ============================================================
// K4: merged scan2+scan3
// ============================================================
__global__ void scan23_all() {
    __shared__ int p[128];
    int t, lb, n;
    const int* deg;
    int* out;
    scan_map(blockIdx.x, t, lb, deg, out, n);
    int tt = threadIdx.x;
    if (tt < 128) p[tt] = (tt < lb) ? g_part[t * 128 + tt] : 0;
    __syncthreads();
    #pragma unroll
    for (int d = 64; d > 0; d >>= 1) {
        if (tt < d) p[tt] += p[tt + d];
        __syncthreads();
    }
    int carry = p[0];
    int i = lb * 1024 + tt;
    if (i < n) out[i] += carry;
}

// ============================================================
// K5: fill CSR edge lists, all types
// ============================================================
__global__ void fill_all(const int* __restrict__ svc_src, const int* __restrict__ svc_dst,
                         const int* __restrict__ pn_src,  const int* __restrict__ pn_dst,
                         const int* __restrict__ np_src,  const int* __restrict__ np_dst,
                         int E_svc, int E_pn, int E_np) {
    int i = blockIdx.x * blockDim.x + threadIdx.x;
    if (i < E_svc) {
        int d = svc_dst[i];
        int p = atomicAdd(&g_fill[OFF_SVC + d], 1);
        g_eidx_svc[g_off[OFF_SVC + d] + p] = svc_src[i];
    } else if (i < E_svc + E_pn) {
        int e = i - E_svc;
        int d = pn_dst[e];
        int p = atomicAdd(&g_fill[OFF_NODE + d], 1);
        g_eidx_pn[g_off[OFF_NODE + d] + p] = pn_src[e];
    } else if (i < E_svc + E_pn + E_np) {
        int e = i - E_svc - E_pn;
        int d = np_dst[e];
        int p = atomicAdd(&g_fill[OFF_POD + d], 1);
        g_eidx_np[g_off[OFF_POD + d] + p] = np_src[e];
    }
}

// ============================================================
// K6: warp-per-dst-row gather (fp32 — R10 form, reverted)
// ============================================================
__global__ void gather_all(const float* __restrict__ x_svc,
                           const float* __restrict__ x_pod,
                           const float* __restrict__ x_node) {
    int w = (blockIdx.x * blockDim.x + threadIdx.x) >> 5;
    int lane = threadIdx.x & 31;
    if (w >= OFF_TOTAL) return;

    const float* x;
    const int* eidx;
    const int* off;
    const int* cnt;
    const float* nsrc;
    const float* ndst;
    float* agg;
    int local;
    if (w < NSVC) {
        local = w;
        x = x_svc; eidx = g_eidx_svc; off = g_off + OFF_SVC;
        cnt = g_deg + DEG_SVC_DST; nsrc = g_nrm + DEG_SVC_SRC; ndst = g_nrm + DEG_SVC_DST;
        agg = g_agg + AGG_SVC_OFF;
    } else if (w < NSVC + NNODE) {
        local = w - NSVC;
        x = x_pod; eidx = g_eidx_pn; off = g_off + OFF_NODE;
        cnt = g_deg + DEG_PN_DST; nsrc = g_nrm + DEG_PN_SRC; ndst = g_nrm + DEG_PN_DST;
        agg = g_agg + AGG_NODE_OFF;
    } else {
        local = w - NSVC - NNODE;
        x = x_node; eidx = g_eidx_np; off = g_off + OFF_POD;
        cnt = g_deg + DEG_NP_DST; nsrc = g_nrm + DEG_NP_SRC; ndst = g_nrm + DEG_NP_DST;
        agg = g_agg + AGG_POD_OFF;
    }

    int beg = off[local];
    int end = beg + cnt[local];
    const float4* x4 = reinterpret_cast<const float4*>(x);

    float4 acc = make_float4(0.f, 0.f, 0.f, 0.f);
    int e = beg;
    for (; e + 4 <= end; e += 4) {
        int s0 = __ldg(eidx + e + 0);
        int s1 = __ldg(eidx + e + 1);
        int s2 = __ldg(eidx + e + 2);
        int s3 = __ldg(eidx + e + 3);
        float n0 = __ldg(nsrc + s0);
        float n1 = __ldg(nsrc + s1);
        float n2 = __ldg(nsrc + s2);
        float n3 = __ldg(nsrc + s3);
        float4 v0 = x4[(size_t)s0 * 32 + lane];
        float4 v1 = x4[(size_t)s1 * 32 + lane];
        float4 v2 = x4[(size_t)s2 * 32 + lane];
        float4 v3 = x4[(size_t)s3 * 32 + lane];
        acc.x += v0.x * n0; acc.y += v0.y * n0; acc.z += v0.z * n0; acc.w += v0.w * n0;
        acc.x += v1.x * n1; acc.y += v1.y * n1; acc.z += v1.z * n1; acc.w += v1.w * n1;
        acc.x += v2.x * n2; acc.y += v2.y * n2; acc.z += v2.z * n2; acc.w += v2.w * n2;
        acc.x += v3.x * n3; acc.y += v3.y * n3; acc.z += v3.z * n3; acc.w += v3.w * n3;
    }
    for (; e < end; e++) {
        int s0 = __ldg(eidx + e);
        float n0 = __ldg(nsrc + s0);
        float4 v0 = x4[(size_t)s0 * 32 + lane];
        acc.x += v0.x * n0; acc.y += v0.y * n0; acc.z += v0.z * n0; acc.w += v0.w * n0;
    }
    float nd = ndst[local];
    reinterpret_cast<float4*>(agg)[(size_t)local * 32 + lane] =
        make_float4(acc.x * nd, acc.y * nd, acc.z * nd, acc.w * nd);
}

// ============================================================
// K7: fused mma.sync PLAIN fp16 GEMM (1 product), 2 blocks/SM
//   D1 = A16@W1h ; h = leaky(D1 + b1) -> fp16
//   D2 = h16@W2h ; out = D2 + b2
// ============================================================
#define SROWB 272
#define SM_A    0
#define SM_W1H  34816
#define SM_W2H  69632
#define SM_B1   87040
#define SM_B2   87552
#define SM_TOTAL 87808

__device__ __forceinline__ uint32_t pack_h2(__half a, __half b) {
    return (uint32_t)__half_as_ushort(a) | ((uint32_t)__half_as_ushort(b) << 16);
}
__device__ __forceinline__ void mma_f16(float* c, uint32_t a0, uint32_t a1,
                                        uint32_t a2, uint32_t a3,
                                        uint32_t b0, uint32_t b1) {
    asm volatile(
        "mma.sync.aligned.m16n8k16.row.col.f32.f16.f16.f32 "
        "{%0,%1,%2,%3}, {%4,%5,%6,%7}, {%8,%9}, {%0,%1,%2,%3};"
        : "+f"(c[0]), "+f"(c[1]), "+f"(c[2]), "+f"(c[3])
        : "r"(a0), "r"(a1), "r"(a2), "r"(a3), "r"(b0), "r"(b1));
}
__device__ __forceinline__ uint32_t lds_u32(const char* base, int row, int col) {
    return *(const uint32_t*)(base + row * SROWB + col * 2);
}

__global__ void __launch_bounds__(256, 2)
gemm_all(const float* __restrict__ b_call, const float* __restrict__ b_lin_svc,
         const float* __restrict__ b_in,   const float* __restrict__ b_lin_node,
         const float* __restrict__ b_ni,   const float* __restrict__ b_lin_pod,
         float* __restrict__ out_base) {
    extern __shared__ char sm[];
    int tid = threadIdx.x;
    int wid = tid >> 5;
    int lane = tid & 31;
    int g = lane >> 2;
    int tig = lane & 3;

    int b = blockIdx.x;
    int t, lb, M;
    const float* agg;
    const float* b1;
    const float* b2;
    float* out;
    if (b < GB_SVC) {
        t = 0; lb = b; M = NSVC;
        agg = g_agg + AGG_SVC_OFF; b1 = b_call; b2 = b_lin_svc;
        out = out_base;
    } else if (b < GB_SVC + GB_NODE) {
        t = 1; lb = b - GB_SVC; M = NNODE;
        agg = g_agg + AGG_NODE_OFF; b1 = b_in; b2 = b_lin_node;
        out = out_base + (size_t)NSVC * OUTD;
    } else {
        t = 2; lb = b - GB_SVC - GB_NODE; M = NPOD;
        agg = g_agg + AGG_POD_OFF; b1 = b_ni; b2 = b_lin_pod;
        out = out_base + (size_t)(NSVC + NNODE) * OUTD;
    }

    // ---- stage weights ----
    {
        const uint4* s1 = (const uint4*)g_w1h[t];
        #pragma unroll
        for (int i = 0; i < 8; i++) {
            int idx = i * 256 + tid;
            int row = idx >> 4, gq = idx & 15;
            *(uint4*)(sm + SM_W1H + row * SROWB + gq * 16) = s1[idx];
        }
        const uint4* s2 = (const uint4*)g_w2h[t];
        #pragma unroll
        for (int i = 0; i < 4; i++) {
            int idx = i * 256 + tid;
            int row = idx >> 4, gq = idx & 15;
            *(uint4*)(sm + SM_W2H + row * SROWB + gq * 16) = s2[idx];
        }
    }
    if (tid < 128) ((float*)(sm + SM_B1))[tid] = b1[tid];
    else if (tid < 192) ((float*)(sm + SM_B2))[tid - 128] = b2[tid - 128];

    // ---- load A tile, convert to fp16 ----
    {
        int row = tid >> 1;
        int half = (tid & 1) * 64;
        int grow = lb * 128 + row;
        const float4* av = (const float4*)agg + (size_t)grow * 32 + (half >> 2);
        #pragma unroll
        for (int j = 0; j < 16; j++) {
            float4 v = (grow < M) ? av[j] : make_float4(0.f, 0.f, 0.f, 0.f);
            __half h0 = __float2half_rn(v.x);
            __half h1 = __float2half_rn(v.y);
            __half h2 = __float2half_rn(v.z);
            __half h3 = __float2half_rn(v.w);
            int col = half + j * 4;
            *(uint2*)(sm + SM_A + row * SROWB + col * 2) =
                make_uint2(pack_h2(h0, h1), pack_h2(h2, h3));
        }
    }
    __syncthreads();

    int mtb = (wid & 3) * 2;
    int nb1 = (wid >> 2) * 64;

    // ---- GEMM1 ----
    float acc[2][8][4];
    #pragma unroll
    for (int mt = 0; mt < 2; mt++)
        #pragma unroll
        for (int nt = 0; nt < 8; nt++)
            #pragma unroll
            for (int q = 0; q < 4; q++) acc[mt][nt][q] = 0.f;

    #pragma unroll
    for (int kc = 0; kc < 8; kc++) {
        int k0 = kc * 16 + tig * 2;
        uint32_t ah[2][4];
        #pragma unroll
        for (int mt = 0; mt < 2; mt++) {
            int r = (mtb + mt) * 16 + g;
            ah[mt][0] = lds_u32(sm + SM_A, r,     k0);
            ah[mt][1] = lds_u32(sm + SM_A, r + 8, k0);
            ah[mt][2] = lds_u32(sm + SM_A, r,     k0 + 8);
            ah[mt][3] = lds_u32(sm + SM_A, r + 8, k0 + 8);
        }
        #pragma unroll
        for (int nt = 0; nt < 8; nt++) {
            int n = nb1 + nt * 8 + g;
            uint32_t bh0 = lds_u32(sm + SM_W1H, n, k0);
            uint32_t bh1 = lds_u32(sm + SM_W1H, n, k0 + 8);
            #pragma unroll
            for (int mt = 0; mt < 2; mt++)
                mma_f16(acc[mt][nt], ah[mt][0], ah[mt][1], ah[mt][2], ah[mt][3], bh0, bh1);
        }
    }
    __syncthreads();

    // ---- epilogue1: bias + leaky -> fp16 into A ----
    {
        const float* b1s = (const float*)(sm + SM_B1);
        #pragma unroll
        for (int mt = 0; mt < 2; mt++) {
            #pragma unroll
            for (int nt = 0; nt < 8; nt++) {
                int row = (mtb + mt) * 16 + g;
                int col = nb1 + nt * 8 + tig * 2;
                float bb0 = b1s[col], bb1 = b1s[col + 1];
                float v0 = acc[mt][nt][0] + bb0;
                float v1 = acc[mt][nt][1] + bb1;
                float v2 = acc[mt][nt][2] + bb0;
                float v3 = acc[mt][nt][3] + bb1;
                v0 = v0 > 0.f ? v0 : 0.01f * v0;
                v1 = v1 > 0.f ? v1 : 0.01f * v1;
                v2 = v2 > 0.f ? v2 : 0.01f * v2;
                v3 = v3 > 0.f ? v3 : 0.01f * v3;
                *(uint32_t*)(sm + SM_A + row * SROWB + col * 2) =
                    pack_h2(__float2half_rn(v0), __float2half_rn(v1));
                *(uint32_t*)(sm + SM_A + (row + 8) * SROWB + col * 2) =
                    pack_h2(__float2half_rn(v2), __float2half_rn(v3));
            }
        }
    }
    __syncthreads();

    // ---- GEMM2 ----
    int nb2 = (wid >> 2) * 32;
    float acc2[2][4][4];
    #pragma unroll
    for (int mt = 0; mt < 2; mt++)
        #pragma unroll
        for (int nt = 0; nt < 4; nt++)
            #pragma unroll
            for (int q = 0; q < 4; q++) acc2[mt][nt][q] = 0.f;

    #pragma unroll
    for (int kc = 0; kc < 8; kc++) {
        int k0 = kc * 16 + tig * 2;
        uint32_t ah[2][4];
        #pragma unroll
        for (int mt = 0; mt < 2; mt++) {
            int r = (mtb + mt) * 16 + g;
            ah[mt][0] = lds_u32(sm + SM_A, r,     k0);
            ah[mt][1] = lds_u32(sm + SM_A, r + 8, k0);
            ah[mt][2] = lds_u32(sm + SM_A, r,     k0 + 8);
            ah[mt][3] = lds_u32(sm + SM_A, r + 8, k0 + 8);
        }
        #pragma unroll
        for (int nt = 0; nt < 4; nt++) {
            int n = nb2 + nt * 8 + g;
            uint32_t bh0 = lds_u32(sm + SM_W2H, n, k0);
            uint32_t bh1 = lds_u32(sm + SM_W2H, n, k0 + 8);
            #pragma unroll
            for (int mt = 0; mt < 2; mt++)
                mma_f16(acc2[mt][nt], ah[mt][0], ah[mt][1], ah[mt][2], ah[mt][3], bh0, bh1);
        }
    }

    // ---- epilogue2 ----
    {
        const float* b2s = (const float*)(sm + SM_B2);
        #pragma unroll
        for (int mt = 0; mt < 2; mt++) {
            #pragma unroll
            for (int nt = 0; nt < 4; nt++) {
                int row = lb * 128 + (mtb + mt) * 16 + g;
                int col = nb2 + nt * 8 + tig * 2;
                float bb0 = b2s[col], bb1 = b2s[col + 1];
                if (row < M)
                    *(float2*)(out + (size_t)row * 64 + col) =
                        make_float2(acc2[mt][nt][0] + bb0, acc2[mt][nt][1] + bb1);
                if (row + 8 < M)
                    *(float2*)(out + (size_t)(row + 8) * 64 + col) =
                        make_float2(acc2[mt][nt][2] + bb0, acc2[mt][nt][3] + bb1);
            }
        }
    }
}

// ============================================================
// launch — 7 kernels total
// ============================================================
extern "C" void kernel_launch(void* const* d_in, const int* in_sizes, int n_in,
                              void* d_out, int out_size) {
    const float* x_svc  = (const float*)d_in[0];
    const float* x_pod  = (const float*)d_in[1];
    const float* x_node = (const float*)d_in[2];
    const int* svc_src = (const int*)d_in[3];
    const int* svc_dst = (const int*)d_in[4];
    const int* pn_src  = (const int*)d_in[5];
    const int* pn_dst  = (const int*)d_in[6];
    const int* np_src  = (const int*)d_in[7];
    const int* np_dst  = (const int*)d_in[8];
    const float* W_call = (const float*)d_in[9];
    const float* b_call = (const float*)d_in[10];
    const float* W_in   = (const float*)d_in[11];
    const float* b_in   = (const float*)d_in[12];
    const float* W_ni   = (const float*)d_in[13];
    const float* b_ni   = (const float*)d_in[14];
    const float* W_lin_svc  = (const float*)d_in[15];
    const float* b_lin_svc  = (const float*)d_in[16];
    const float* W_lin_node = (const float*)d_in[17];
    const float* b_lin_node = (const float*)d_in[18];
    const float* W_lin_pod  = (const float*)d_in[19];
    const float* b_lin_pod  = (const float*)d_in[20];
    float* out = (float*)d_out;

    int E_svc = in_sizes[3];
    int E_pn  = in_sizes[5];
    int E_np  = in_sizes[7];
    int E_tot = E_svc + E_pn + E_np;

    cudaFuncSetAttribute(gemm_all, cudaFuncAttributeMaxDynamicSharedMemorySize, SM_TOTAL);

    prep0<<<512, 256>>>(W_call, W_lin_svc, W_in, W_lin_node, W_ni, W_lin_pod);

    deg_all<<<(E_tot + 255) / 256, 256>>>(svc_src, svc_dst, pn_src, pn_dst,
                                          np_src, np_dst, E_svc, E_pn, E_np);

    scan1_all<<<NB_ALL, 1024>>>();
    scan23_all<<<NB_ALL, 1024>>>();

    fill_all<<<(E_tot + 255) / 256, 256>>>(svc_src, svc_dst, pn_src, pn_dst,
                                           np_src, np_dst, E_svc, E_pn, E_np);

    gather_all<<<(OFF_TOTAL + 7) / 8, 256>>>(x_svc, x_pod, x_node);

    gemm_all<<<GB_ALL, 256, SM_TOTAL>>>(b_call, b_lin_svc, b_in, b_lin_node,
                                        b_ni, b_lin_pod, out);
}

// round 13
// speedup vs baseline: 1.2358x; 1.0278x over previous
#include <cuda_runtime.h>
#include <cuda_fp16.h>
#include <cstdint>

#define NSVC 50000
#define NNODE 20000
#define NPOD 100000
#define FD 128
#define OUTD 64
#define ESVC_MAX 1600000
#define EPN_MAX  100000
#define ENP_MAX  100000

// ---- degree/norm array layout ----
#define DEG_SVC_SRC 0
#define DEG_SVC_DST (NSVC)
#define DEG_PN_SRC  (2*NSVC)
#define DEG_PN_DST  (2*NSVC + NPOD)
#define DEG_NP_SRC  (2*NSVC + NPOD + NNODE)
#define DEG_NP_DST  (2*NSVC + NPOD + 2*NNODE)
#define DEG_TOTAL   (2*NSVC + 2*NPOD + 2*NNODE)

#define OFF_SVC  0
#define OFF_NODE (NSVC)
#define OFF_POD  (NSVC + NNODE)
#define OFF_TOTAL (NSVC + NNODE + NPOD)

#define AGG_SVC_OFF  ((size_t)0)
#define AGG_NODE_OFF ((size_t)NSVC * FD)
#define AGG_POD_OFF  ((size_t)(NSVC + NNODE) * FD)
#define AGG_TOTAL    ((size_t)(NSVC + NNODE + NPOD) * FD)

// scan block mapping (1024-wide blocks)
#define NB_SVC  49
#define NB_NODE 20
#define NB_POD  98
#define NB_ALL  167

// gemm block mapping (128 rows/block)
#define GB_SVC  391
#define GB_NODE 157
#define GB_POD  782
#define GB_ALL  1330

__device__ float g_agg[AGG_TOTAL];
__device__ int   g_deg[DEG_TOTAL];
__device__ float g_nrm[DEG_TOTAL];
__device__ int   g_off[OFF_TOTAL];
__device__ int   g_fill[OFF_TOTAL];
__device__ int   g_part[3 * 128];
__device__ int   g_eidx_svc[ESVC_MAX];
__device__ int   g_eidx_pn[EPN_MAX];
__device__ int   g_eidx_np[ENP_MAX];

// fp16 weights (transposed [n][k])
__device__ __half g_w1h[3][128 * 128];
__device__ __half g_w2h[3][64 * 128];

// ============================================================
// K1: zero counters + weight conversion (fused)
// ============================================================
__global__ void prep0(const float* __restrict__ W1_0, const float* __restrict__ W2_0,
                      const float* __restrict__ W1_1, const float* __restrict__ W2_1,
                      const float* __restrict__ W1_2, const float* __restrict__ W2_2) {
    int tid0 = blockIdx.x * blockDim.x + threadIdx.x;
    int stride = gridDim.x * blockDim.x;
    for (int i = tid0; i < DEG_TOTAL; i += stride) g_deg[i] = 0;
    for (int i = tid0; i < OFF_TOTAL; i += stride) g_fill[i] = 0;

    int idx = tid0;
    if (idx < 73728) {
        int t = idx / 24576;
        int r = idx % 24576;
        const float* W1 = (t == 0) ? W1_0 : (t == 1) ? W1_1 : W1_2;
        const float* W2 = (t == 0) ? W2_0 : (t == 1) ? W2_1 : W2_2;
        if (r < 16384) {
            int n = r >> 7, k = r & 127;
            g_w1h[t][n * 128 + k] = __float2half_rn(__ldg(W1 + k * 128 + n));
        } else {
            int q = r - 16384;
            int n = q >> 7, k = q & 127;
            g_w2h[t][n * 128 + k] = __float2half_rn(__ldg(W2 + k * 64 + n));
        }
    }
}

// ============================================================
// K2: degree counting, all three edge types in one grid
// ============================================================
__global__ void deg_all(const int* __restrict__ svc_src, const int* __restrict__ svc_dst,
                        const int* __restrict__ pn_src,  const int* __restrict__ pn_dst,
                        const int* __restrict__ np_src,  const int* __restrict__ np_dst,
                        int E_svc, int E_pn, int E_np) {
    int i = blockIdx.x * blockDim.x + threadIdx.x;
    if (i < E_svc) {
        atomicAdd(&g_deg[DEG_SVC_SRC + svc_src[i]], 1);
        atomicAdd(&g_deg[DEG_SVC_DST + svc_dst[i]], 1);
    } else if (i < E_svc + E_pn) {
        int e = i - E_svc;
        atomicAdd(&g_deg[DEG_PN_SRC + pn_src[e]], 1);
        atomicAdd(&g_deg[DEG_PN_DST + pn_dst[e]], 1);
    } else if (i < E_svc + E_pn + E_np) {
        int e = i - E_svc - E_pn;
        atomicAdd(&g_deg[DEG_NP_SRC + np_src[e]], 1);
        atomicAdd(&g_deg[DEG_NP_DST + np_dst[e]], 1);
    }
}

// ============================================================
// K3: per-type block scan (stage 1) + nrm computation
// ============================================================
__device__ __forceinline__ void scan_map(int b, int& t, int& lb,
                                         const int*& deg, int*& out, int& n) {
    if (b < NB_SVC)             { t = 0; lb = b;                    deg = g_deg + DEG_SVC_DST; out = g_off + OFF_SVC;  n = NSVC; }
    else if (b < NB_SVC+NB_NODE){ t = 1; lb = b - NB_SVC;           deg = g_deg + DEG_PN_DST;  out = g_off + OFF_NODE; n = NNODE; }
    else                        { t = 2; lb = b - NB_SVC - NB_NODE; deg = g_deg + DEG_NP_DST;  out = g_off + OFF_POD;  n = NPOD; }
}

__global__ void scan1_all() {
    {
        int tid0 = blockIdx.x * blockDim.x + threadIdx.x;
        int stride = gridDim.x * blockDim.x;
        for (int i = tid0; i < DEG_TOTAL; i += stride) {
            int d = g_deg[i];
            g_nrm[i] = rsqrtf((float)(d > 1 ? d : 1));
        }
    }
    __shared__ int s[1024];
    int t, lb, n;
    const int* deg;
    int* out;
    scan_map(blockIdx.x, t, lb, deg, out, n);
    int tt = threadIdx.x;
    int i = lb * 1024 + tt;
    int v = (i < n) ? deg[i] : 0;
    s[tt] = v;
    __syncthreads();
    #pragma unroll
    for (int d = 1; d < 1024; d <<= 1) {
        int tv = (tt >= d) ? s[tt - d] : 0;
        __syncthreads();
        s[tt] += tv;
        __syncthreads();
    }
    if (i < n) out[i] = s[tt] - v;
    if (tt == 1023) g_part[t * 128 + lb] = s[tt];
}

// ============================================================
// K4: merged scan2+scan3
// ============================================================
__global__ void scan23_all() {
    __shared__ int p[128];
    int t, lb, n;
    const int* deg;
    int* out;
    scan_map(blockIdx.x, t, lb, deg, out, n);
    int tt = threadIdx.x;
    if (tt < 128) p[tt] = (tt < lb) ? g_part[t * 128 + tt] : 0;
    __syncthreads();
    #pragma unroll
    for (int d = 64; d > 0; d >>= 1) {
        if (tt < d) p[tt] += p[tt + d];
        __syncthreads();
    }
    int carry = p[0];
    int i = lb * 1024 + tt;
    if (i < n) out[i] += carry;
}

// ============================================================
// K5: fill CSR edge lists, all types
// ============================================================
__global__ void fill_all(const int* __restrict__ svc_src, const int* __restrict__ svc_dst,
                         const int* __restrict__ pn_src,  const int* __restrict__ pn_dst,
                         const int* __restrict__ np_src,  const int* __restrict__ np_dst,
                         int E_svc, int E_pn, int E_np) {
    int i = blockIdx.x * blockDim.x + threadIdx.x;
    if (i < E_svc) {
        int d = svc_dst[i];
        int p = atomicAdd(&g_fill[OFF_SVC + d], 1);
        g_eidx_svc[g_off[OFF_SVC + d] + p] = svc_src[i];
    } else if (i < E_svc + E_pn) {
        int e = i - E_svc;
        int d = pn_dst[e];
        int p = atomicAdd(&g_fill[OFF_NODE + d], 1);
        g_eidx_pn[g_off[OFF_NODE + d] + p] = pn_src[e];
    } else if (i < E_svc + E_pn + E_np) {
        int e = i - E_svc - E_pn;
        int d = np_dst[e];
        int p = atomicAdd(&g_fill[OFF_POD + d], 1);
        g_eidx_np[g_off[OFF_POD + d] + p] = np_src[e];
    }
}

// ============================================================
// K6: warp-per-dst-row gather, 8-wide batched MLP
// ============================================================
__global__ void gather_all(const float* __restrict__ x_svc,
                           const float* __restrict__ x_pod,
                           const float* __restrict__ x_node) {
    int w = (blockIdx.x * blockDim.x + threadIdx.x) >> 5;
    int lane = threadIdx.x & 31;
    if (w >= OFF_TOTAL) return;

    const float* x;
    const int* eidx;
    const int* off;
    const int* cnt;
    const float* nsrc;
    const float* ndst;
    float* agg;
    int local;
    if (w < NSVC) {
        local = w;
        x = x_svc; eidx = g_eidx_svc; off = g_off + OFF_SVC;
        cnt = g_deg + DEG_SVC_DST; nsrc = g_nrm + DEG_SVC_SRC; ndst = g_nrm + DEG_SVC_DST;
        agg = g_agg + AGG_SVC_OFF;
    } else if (w < NSVC + NNODE) {
        local = w - NSVC;
        x = x_pod; eidx = g_eidx_pn; off = g_off + OFF_NODE;
        cnt = g_deg + DEG_PN_DST; nsrc = g_nrm + DEG_PN_SRC; ndst = g_nrm + DEG_PN_DST;
        agg = g_agg + AGG_NODE_OFF;
    } else {
        local = w - NSVC - NNODE;
        x = x_node; eidx = g_eidx_np; off = g_off + OFF_POD;
        cnt = g_deg + DEG_NP_DST; nsrc = g_nrm + DEG_NP_SRC; ndst = g_nrm + DEG_NP_DST;
        agg = g_agg + AGG_POD_OFF;
    }

    int beg = off[local];
    int end = beg + cnt[local];
    const float4* x4 = reinterpret_cast<const float4*>(x);

    float4 acc = make_float4(0.f, 0.f, 0.f, 0.f);
    int e = beg;
    for (; e + 8 <= end; e += 8) {
        int s[8];
        #pragma unroll
        for (int j = 0; j < 8; j++) s[j] = __ldg(eidx + e + j);
        float n[8];
        #pragma unroll
        for (int j = 0; j < 8; j++) n[j] = __ldg(nsrc + s[j]);
        float4 v[8];
        #pragma unroll
        for (int j = 0; j < 8; j++) v[j] = x4[(size_t)s[j] * 32 + lane];
        #pragma unroll
        for (int j = 0; j < 8; j++) {
            acc.x += v[j].x * n[j];
            acc.y += v[j].y * n[j];
            acc.z += v[j].z * n[j];
            acc.w += v[j].w * n[j];
        }
    }
    if (e + 4 <= end) {
        int s[4];
        #pragma unroll
        for (int j = 0; j < 4; j++) s[j] = __ldg(eidx + e + j);
        float n[4];
        #pragma unroll
        for (int j = 0; j < 4; j++) n[j] = __ldg(nsrc + s[j]);
        float4 v[4];
        #pragma unroll
        for (int j = 0; j < 4; j++) v[j] = x4[(size_t)s[j] * 32 + lane];
        #pragma unroll
        for (int j = 0; j < 4; j++) {
            acc.x += v[j].x * n[j];
            acc.y += v[j].y * n[j];
            acc.z += v[j].z * n[j];
            acc.w += v[j].w * n[j];
        }
        e += 4;
    }
    for (; e < end; e++) {
        int s0 = __ldg(eidx + e);
        float n0 = __ldg(nsrc + s0);
        float4 v0 = x4[(size_t)s0 * 32 + lane];
        acc.x += v0.x * n0; acc.y += v0.y * n0; acc.z += v0.z * n0; acc.w += v0.w * n0;
    }
    float nd = ndst[local];
    reinterpret_cast<float4*>(agg)[(size_t)local * 32 + lane] =
        make_float4(acc.x * nd, acc.y * nd, acc.z * nd, acc.w * nd);
}

// ============================================================
// K7: fused mma.sync plain fp16 GEMM, 2 blocks/SM (R12 form)
// ============================================================
#define SROWB 272
#define SM_A    0
#define SM_W1H  34816
#define SM_W2H  69632
#define SM_B1   87040
#define SM_B2   87552
#define SM_TOTAL 87808

__device__ __forceinline__ uint32_t pack_h2(__half a, __half b) {
    return (uint32_t)__half_as_ushort(a) | ((uint32_t)__half_as_ushort(b) << 16);
}
__device__ __forceinline__ void mma_f16(float* c, uint32_t a0, uint32_t a1,
                                        uint32_t a2, uint32_t a3,
                                        uint32_t b0, uint32_t b1) {
    asm volatile(
        "mma.sync.aligned.m16n8k16.row.col.f32.f16.f16.f32 "
        "{%0,%1,%2,%3}, {%4,%5,%6,%7}, {%8,%9}, {%0,%1,%2,%3};"
        : "+f"(c[0]), "+f"(c[1]), "+f"(c[2]), "+f"(c[3])
        : "r"(a0), "r"(a1), "r"(a2), "r"(a3), "r"(b0), "r"(b1));
}
__device__ __forceinline__ uint32_t lds_u32(const char* base, int row, int col) {
    return *(const uint32_t*)(base + row * SROWB + col * 2);
}

__global__ void __launch_bounds__(256, 2)
gemm_all(const float* __restrict__ b_call, const float* __restrict__ b_lin_svc,
         const float* __restrict__ b_in,   const float* __restrict__ b_lin_node,
         const float* __restrict__ b_ni,   const float* __restrict__ b_lin_pod,
         float* __restrict__ out_base) {
    extern __shared__ char sm[];
    int tid = threadIdx.x;
    int wid = tid >> 5;
    int lane = tid & 31;
    int g = lane >> 2;
    int tig = lane & 3;

    int b = blockIdx.x;
    int t, lb, M;
    const float* agg;
    const float* b1;
    const float* b2;
    float* out;
    if (b < GB_SVC) {
        t = 0; lb = b; M = NSVC;
        agg = g_agg + AGG_SVC_OFF; b1 = b_call; b2 = b_lin_svc;
        out = out_base;
    } else if (b < GB_SVC + GB_NODE) {
        t = 1; lb = b - GB_SVC; M = NNODE;
        agg = g_agg + AGG_NODE_OFF; b1 = b_in; b2 = b_lin_node;
        out = out_base + (size_t)NSVC * OUTD;
    } else {
        t = 2; lb = b - GB_SVC - GB_NODE; M = NPOD;
        agg = g_agg + AGG_POD_OFF; b1 = b_ni; b2 = b_lin_pod;
        out = out_base + (size_t)(NSVC + NNODE) * OUTD;
    }

    // ---- stage weights ----
    {
        const uint4* s1 = (const uint4*)g_w1h[t];
        #pragma unroll
        for (int i = 0; i < 8; i++) {
            int idx = i * 256 + tid;
            int row = idx >> 4, gq = idx & 15;
            *(uint4*)(sm + SM_W1H + row * SROWB + gq * 16) = s1[idx];
        }
        const uint4* s2 = (const uint4*)g_w2h[t];
        #pragma unroll
        for (int i = 0; i < 4; i++) {
            int idx = i * 256 + tid;
            int row = idx >> 4, gq = idx & 15;
            *(uint4*)(sm + SM_W2H + row * SROWB + gq * 16) = s2[idx];
        }
    }
    if (tid < 128) ((float*)(sm + SM_B1))[tid] = b1[tid];
    else if (tid < 192) ((float*)(sm + SM_B2))[tid - 128] = b2[tid - 128];

    // ---- load A tile, convert to fp16 ----
    {
        int row = tid >> 1;
        int half = (tid & 1) * 64;
        int grow = lb * 128 + row;
        const float4* av = (const float4*)agg + (size_t)grow * 32 + (half >> 2);
        #pragma unroll
        for (int j = 0; j < 16; j++) {
            float4 v = (grow < M) ? av[j] : make_float4(0.f, 0.f, 0.f, 0.f);
            __half h0 = __float2half_rn(v.x);
            __half h1 = __float2half_rn(v.y);
            __half h2 = __float2half_rn(v.z);
            __half h3 = __float2half_rn(v.w);
            int col = half + j * 4;
            *(uint2*)(sm + SM_A + row * SROWB + col * 2) =
                make_uint2(pack_h2(h0, h1), pack_h2(h2, h3));
        }
    }
    __syncthreads();

    int mtb = (wid & 3) * 2;
    int nb1 = (wid >> 2) * 64;

    // ---- GEMM1 ----
    float acc[2][8][4];
    #pragma unroll
    for (int mt = 0; mt < 2; mt++)
        #pragma unroll
        for (int nt = 0; nt < 8; nt++)
            #pragma unroll
            for (int q = 0; q < 4; q++) acc[mt][nt][q] = 0.f;

    #pragma unroll
    for (int kc = 0; kc < 8; kc++) {
        int k0 = kc * 16 + tig * 2;
        uint32_t ah[2][4];
        #pragma unroll
        for (int mt = 0; mt < 2; mt++) {
            int r = (mtb + mt) * 16 + g;
            ah[mt][0] = lds_u32(sm + SM_A, r,     k0);
            ah[mt][1] = lds_u32(sm + SM_A, r + 8, k0);
            ah[mt][2] = lds_u32(sm + SM_A, r,     k0 + 8);
            ah[mt][3] = lds_u32(sm + SM_A, r + 8, k0 + 8);
        }
        #pragma unroll
        for (int nt = 0; nt < 8; nt++) {
            int n = nb1 + nt * 8 + g;
            uint32_t bh0 = lds_u32(sm + SM_W1H, n, k0);
            uint32_t bh1 = lds_u32(sm + SM_W1H, n, k0 + 8);
            #pragma unroll
            for (int mt = 0; mt < 2; mt++)
                mma_f16(acc[mt][nt], ah[mt][0], ah[mt][1], ah[mt][2], ah[mt][3], bh0, bh1);
        }
    }
    __syncthreads();

    // ---- epilogue1: bias + leaky -> fp16 into A ----
    {
        const float* b1s = (const float*)(sm + SM_B1);
        #pragma unroll
        for (int mt = 0; mt < 2; mt++) {
            #pragma unroll
            for (int nt = 0; nt < 8; nt++) {
                int row = (mtb + mt) * 16 + g;
                int col = nb1 + nt * 8 + tig * 2;
                float bb0 = b1s[col], bb1 = b1s[col + 1];
                float v0 = acc[mt][nt][0] + bb0;
                float v1 = acc[mt][nt][1] + bb1;
                float v2 = acc[mt][nt][2] + bb0;
                float v3 = acc[mt][nt][3] + bb1;
                v0 = v0 > 0.f ? v0 : 0.01f * v0;
                v1 = v1 > 0.f ? v1 : 0.01f * v1;
                v2 = v2 > 0.f ? v2 : 0.01f * v2;
                v3 = v3 > 0.f ? v3 : 0.01f * v3;
                *(uint32_t*)(sm + SM_A + row * SROWB + col * 2) =
                    pack_h2(__float2half_rn(v0), __float2half_rn(v1));
                *(uint32_t*)(sm + SM_A + (row + 8) * SROWB + col * 2) =
                    pack_h2(__float2half_rn(v2), __float2half_rn(v3));
            }
        }
    }
    __syncthreads();

    // ---- GEMM2 ----
    int nb2 = (wid >> 2) * 32;
    float acc2[2][4][4];
    #pragma unroll
    for (int mt = 0; mt < 2; mt++)
        #pragma unroll
        for (int nt = 0; nt < 4; nt++)
            #pragma unroll
            for (int q = 0; q < 4; q++) acc2[mt][nt][q] = 0.f;

    #pragma unroll
    for (int kc = 0; kc < 8; kc++) {
        int k0 = kc * 16 + tig * 2;
        uint32_t ah[2][4];
        #pragma unroll
        for (int mt = 0; mt < 2; mt++) {
            int r = (mtb + mt) * 16 + g;
            ah[mt][0] = lds_u32(sm + SM_A, r,     k0);
            ah[mt][1] = lds_u32(sm + SM_A, r + 8, k0);
            ah[mt][2] = lds_u32(sm + SM_A, r,     k0 + 8);
            ah[mt][3] = lds_u32(sm + SM_A, r + 8, k0 + 8);
        }
        #pragma unroll
        for (int nt = 0; nt < 4; nt++) {
            int n = nb2 + nt * 8 + g;
            uint32_t bh0 = lds_u32(sm + SM_W2H, n, k0);
            uint32_t bh1 = lds_u32(sm + SM_W2H, n, k0 + 8);
            #pragma unroll
            for (int mt = 0; mt < 2; mt++)
                mma_f16(acc2[mt][nt], ah[mt][0], ah[mt][1], ah[mt][2], ah[mt][3], bh0, bh1);
        }
    }

    // ---- epilogue2 ----
    {
        const float* b2s = (const float*)(sm + SM_B2);
        #pragma unroll
        for (int mt = 0; mt < 2; mt++) {
            #pragma unroll
            for (int nt = 0; nt < 4; nt++) {
                int row = lb * 128 + (mtb + mt) * 16 + g;
                int col = nb2 + nt * 8 + tig * 2;
                float bb0 = b2s[col], bb1 = b2s[col + 1];
                if (row < M)
                    *(float2*)(out + (size_t)row * 64 + col) =
                        make_float2(acc2[mt][nt][0] + bb0, acc2[mt][nt][1] + bb1);
                if (row + 8 < M)
                    *(float2*)(out + (size_t)(row + 8) * 64 + col) =
                        make_float2(acc2[mt][nt][2] + bb0, acc2[mt][nt][3] + bb1);
            }
        }
    }
}

// ============================================================
// launch — 7 kernels total
// ============================================================
extern "C" void kernel_launch(void* const* d_in, const int* in_sizes, int n_in,
                              void* d_out, int out_size) {
    const float* x_svc  = (const float*)d_in[0];
    const float* x_pod  = (const float*)d_in[1];
    const float* x_node = (const float*)d_in[2];
    const int* svc_src = (const int*)d_in[3];
    const int* svc_dst = (const int*)d_in[4];
    const int* pn_src  = (const int*)d_in[5];
    const int* pn_dst  = (const int*)d_in[6];
    const int* np_src  = (const int*)d_in[7];
    const int* np_dst  = (const int*)d_in[8];
    const float* W_call = (const float*)d_in[9];
    const float* b_call = (const float*)d_in[10];
    const float* W_in   = (const float*)d_in[11];
    const float* b_in   = (const float*)d_in[12];
    const float* W_ni   = (const float*)d_in[13];
    const float* b_ni   = (const float*)d_in[14];
    const float* W_lin_svc  = (const float*)d_in[15];
    const float* b_lin_svc  = (const float*)d_in[16];
    const float* W_lin_node = (const float*)d_in[17];
    const float* b_lin_node = (const float*)d_in[18];
    const float* W_lin_pod  = (const float*)d_in[19];
    const float* b_lin_pod  = (const float*)d_in[20];
    float* out = (float*)d_out;

    int E_svc = in_sizes[3];
    int E_pn  = in_sizes[5];
    int E_np  = in_sizes[7];
    int E_tot = E_svc + E_pn + E_np;

    cudaFuncSetAttribute(gemm_all, cudaFuncAttributeMaxDynamicSharedMemorySize, SM_TOTAL);

    prep0<<<512, 256>>>(W_call, W_lin_svc, W_in, W_lin_node, W_ni, W_lin_pod);

    deg_all<<<(E_tot + 255) / 256, 256>>>(svc_src, svc_dst, pn_src, pn_dst,
                                          np_src, np_dst, E_svc, E_pn, E_np);

    scan1_all<<<NB_ALL, 1024>>>();
    scan23_all<<<NB_ALL, 1024>>>();

    fill_all<<<(E_tot + 255) / 256, 256>>>(svc_src, svc_dst, pn_src, pn_dst,
                                           np_src, np_dst, E_svc, E_pn, E_np);

    gather_all<<<(OFF_TOTAL + 7) / 8, 256>>>(x_svc, x_pod, x_node);

    gemm_all<<<GB_ALL, 256, SM_TOTAL>>>(b_call, b_lin_svc, b_in, b_lin_node,
                                        b_ni, b_lin_pod, out);
}

// round 17
// speedup vs baseline: 1.2394x; 1.0029x over previous
#include <cuda_runtime.h>
#include <cuda_fp16.h>
#include <cstdint>

#define NSVC 50000
#define NNODE 20000
#define NPOD 100000
#define FD 128
#define OUTD 64
#define ESVC_MAX 1600000
#define EPN_MAX  100000
#define ENP_MAX  100000

// ---- degree/norm array layout ----
#define DEG_SVC_SRC 0
#define DEG_SVC_DST (NSVC)
#define DEG_PN_SRC  (2*NSVC)
#define DEG_PN_DST  (2*NSVC + NPOD)
#define DEG_NP_SRC  (2*NSVC + NPOD + NNODE)
#define DEG_NP_DST  (2*NSVC + NPOD + 2*NNODE)
#define DEG_TOTAL   (2*NSVC + 2*NPOD + 2*NNODE)

#define OFF_SVC  0
#define OFF_NODE (NSVC)
#define OFF_POD  (NSVC + NNODE)
#define OFF_TOTAL (NSVC + NNODE + NPOD)

#define AGG_SVC_OFF  ((size_t)0)
#define AGG_NODE_OFF ((size_t)NSVC * FD)
#define AGG_POD_OFF  ((size_t)(NSVC + NNODE) * FD)
#define AGG_TOTAL    ((size_t)(NSVC + NNODE + NPOD) * FD)

// pre-scaled fp16 features (rows in input-tensor order)
#define XH_SVC_OFF  ((size_t)0)
#define XH_POD_OFF  ((size_t)NSVC * FD)
#define XH_NODE_OFF ((size_t)(NSVC + NPOD) * FD)
#define XH_TOTAL    ((size_t)(NSVC + NPOD + NNODE) * FD)
#define XH_CHUNKS   (XH_TOTAL / 8)          /* uint4 (8 halves) chunks */

// scan block mapping (1024-wide blocks)
#define NB_SVC  49
#define NB_NODE 20
#define NB_POD  98
#define NB_ALL  167
#define XS_BLOCKS 592                        /* extra 1024-thread blocks for xs conv */

// gemm block mapping (128 rows/block)
#define GB_SVC  391
#define GB_NODE 157
#define GB_POD  782
#define GB_ALL  1330

__device__ float g_agg[AGG_TOTAL];
__device__ __half g_xh[XH_TOTAL];
__device__ int   g_deg[DEG_TOTAL];
__device__ float g_nrm[DEG_TOTAL];
__device__ int   g_off[OFF_TOTAL];
__device__ int   g_fill[OFF_TOTAL];
__device__ int   g_part[3 * 128];
__device__ int   g_eidx_svc[ESVC_MAX];
__device__ int   g_eidx_pn[EPN_MAX];
__device__ int   g_eidx_np[ENP_MAX];

// fp16 weights (transposed [n][k])
__device__ __half g_w1h[3][128 * 128];
__device__ __half g_w2h[3][64 * 128];

// ============================================================
// K1: zero counters + weight conversion (fused)
// ============================================================
__global__ void prep0(const float* __restrict__ W1_0, const float* __restrict__ W2_0,
                      const float* __restrict__ W1_1, const float* __restrict__ W2_1,
                      const float* __restrict__ W1_2, const float* __restrict__ W2_2) {
    int tid0 = blockIdx.x * blockDim.x + threadIdx.x;
    int stride = gridDim.x * blockDim.x;
    for (int i = tid0; i < DEG_TOTAL; i += stride) g_deg[i] = 0;
    for (int i = tid0; i < OFF_TOTAL; i += stride) g_fill[i] = 0;

    int idx = tid0;
    if (idx < 73728) {
        int t = idx / 24576;
        int r = idx % 24576;
        const float* W1 = (t == 0) ? W1_0 : (t == 1) ? W1_1 : W1_2;
        const float* W2 = (t == 0) ? W2_0 : (t == 1) ? W2_1 : W2_2;
        if (r < 16384) {
            int n = r >> 7, k = r & 127;
            g_w1h[t][n * 128 + k] = __float2half_rn(__ldg(W1 + k * 128 + n));
        } else {
            int q = r - 16384;
            int n = q >> 7, k = q & 127;
            g_w2h[t][n * 128 + k] = __float2half_rn(__ldg(W2 + k * 64 + n));
        }
    }
}

// ============================================================
// K2: degree counting, all three edge types in one grid
// ============================================================
__global__ void deg_all(const int* __restrict__ svc_src, const int* __restrict__ svc_dst,
                        const int* __restrict__ pn_src,  const int* __restrict__ pn_dst,
                        const int* __restrict__ np_src,  const int* __restrict__ np_dst,
                        int E_svc, int E_pn, int E_np) {
    int i = blockIdx.x * blockDim.x + threadIdx.x;
    if (i < E_svc) {
        atomicAdd(&g_deg[DEG_SVC_SRC + svc_src[i]], 1);
        atomicAdd(&g_deg[DEG_SVC_DST + svc_dst[i]], 1);
    } else if (i < E_svc + E_pn) {
        int e = i - E_svc;
        atomicAdd(&g_deg[DEG_PN_SRC + pn_src[e]], 1);
        atomicAdd(&g_deg[DEG_PN_DST + pn_dst[e]], 1);
    } else if (i < E_svc + E_pn + E_np) {
        int e = i - E_svc - E_pn;
        atomicAdd(&g_deg[DEG_NP_SRC + np_src[e]], 1);
        atomicAdd(&g_deg[DEG_NP_DST + np_dst[e]], 1);
    }
}

// ============================================================
// K3: per-type block scan (stage 1) + nrm computation
// ============================================================
__device__ __forceinline__ void scan_map(int b, int& t, int& lb,
                                         const int*& deg, int*& out, int& n) {
    if (b < NB_SVC)             { t = 0; lb = b;                    deg = g_deg + DEG_SVC_DST; out = g_off + OFF_SVC;  n = NSVC; }
    else if (b < NB_SVC+NB_NODE){ t = 1; lb = b - NB_SVC;           deg = g_deg + DEG_PN_DST;  out = g_off + OFF_NODE; n = NNODE; }
    else                        { t = 2; lb = b - NB_SVC - NB_NODE; deg = g_deg + DEG_NP_DST;  out = g_off + OFF_POD;  n = NPOD; }
}

__global__ void scan1_all() {
    {
        int tid0 = blockIdx.x * blockDim.x + threadIdx.x;
        int stride = gridDim.x * blockDim.x;
        for (int i = tid0; i < DEG_TOTAL; i += stride) {
            int d = g_deg[i];
            g_nrm[i] = rsqrtf((float)(d > 1 ? d : 1));
        }
    }
    __shared__ int s[1024];
    int t, lb, n;
    const int* deg;
    int* out;
    scan_map(blockIdx.x, t, lb, deg, out, n);
    int tt = threadIdx.x;
    int i = lb * 1024 + tt;
    int v = (i < n) ? deg[i] : 0;
    s[tt] = v;
    __syncthreads();
    #pragma unroll
    for (int d = 1; d < 1024; d <<= 1) {
        int tv = (tt >= d) ? s[tt - d] : 0;
        __syncthreads();
        s[tt] += tv;
        __syncthreads();
    }
    if (i < n) out[i] = s[tt] - v;
    if (tt == 1023) g_part[t * 128 + lb] = s[tt];
}

// ============================================================
// K4: merged scan2+scan3 + xs = x*nsrc fp16 conversion
//   blocks [0, NB_ALL)       : scan fixup
//   blocks [NB_ALL, +XS_BLOCKS): grid-stride xs conversion
// ============================================================
__global__ void scan23x(const float* __restrict__ x_svc,
                        const float* __restrict__ x_pod,
                        const float* __restrict__ x_node) {
    if (blockIdx.x < NB_ALL) {
        __shared__ int p[128];
        int t, lb, n;
        const int* deg;
        int* out;
        scan_map(blockIdx.x, t, lb, deg, out, n);
        int tt = threadIdx.x;
        if (tt < 128) p[tt] = (tt < lb) ? g_part[t * 128 + tt] : 0;
        __syncthreads();
        #pragma unroll
        for (int d = 64; d > 0; d >>= 1) {
            if (tt < d) p[tt] += p[tt + d];
            __syncthreads();
        }
        int carry = p[0];
        int i = lb * 1024 + tt;
        if (i < n) out[i] += carry;
        return;
    }
    // xs conversion: one thread per 8 elements (uint4 of halves)
    size_t base = (size_t)(blockIdx.x - NB_ALL) * blockDim.x + threadIdx.x;
    size_t stride = (size_t)XS_BLOCKS * blockDim.x;
    for (size_t c = base; c < XH_CHUNKS; c += stride) {
        size_t row = c >> 4;            // 16 chunks per 128-col row
        const float* x;
        float ns;
        if (row < NSVC) {
            x = x_svc + row * FD;
            ns = g_nrm[DEG_SVC_SRC + (int)row];
        } else if (row < NSVC + NPOD) {
            size_t r = row - NSVC;
            x = x_pod + r * FD;
            ns = g_nrm[DEG_PN_SRC + (int)r];
        } else {
            size_t r = row - NSVC - NPOD;
            x = x_node + r * FD;
            ns = g_nrm[DEG_NP_SRC + (int)r];
        }
        int col = (int)(c & 15) * 8;
        const float4* s4 = (const float4*)(x + col);
        float4 a = s4[0];
        float4 b = s4[1];
        __half2 h0 = __floats2half2_rn(a.x * ns, a.y * ns);
        __half2 h1 = __floats2half2_rn(a.z * ns, a.w * ns);
        __half2 h2 = __floats2half2_rn(b.x * ns, b.y * ns);
        __half2 h3 = __floats2half2_rn(b.z * ns, b.w * ns);
        ((uint4*)g_xh)[c] = make_uint4(*(uint32_t*)&h0, *(uint32_t*)&h1,
                                       *(uint32_t*)&h2, *(uint32_t*)&h3);
    }
}

// ============================================================
// K5: fill CSR edge lists, all types
// ============================================================
__global__ void fill_all(const int* __restrict__ svc_src, const int* __restrict__ svc_dst,
                         const int* __restrict__ pn_src,  const int* __restrict__ pn_dst,
                         const int* __restrict__ np_src,  const int* __restrict__ np_dst,
                         int E_svc, int E_pn, int E_np) {
    int i = blockIdx.x * blockDim.x + threadIdx.x;
    if (i < E_svc) {
        int d = svc_dst[i];
        int p = atomicAdd(&g_fill[OFF_SVC + d], 1);
        g_eidx_svc[g_off[OFF_SVC + d] + p] = svc_src[i];
    } else if (i < E_svc + E_pn) {
        int e = i - E_svc;
        int d = pn_dst[e];
        int p = atomicAdd(&g_fill[OFF_NODE + d], 1);
        g_eidx_pn[g_off[OFF_NODE + d] + p] = pn_src[e];
    } else if (i < E_svc + E_pn + E_np) {
        int e = i - E_svc - E_pn;
        int d = np_dst[e];
        int p = atomicAdd(&g_fill[OFF_POD + d], 1);
        g_eidx_np[g_off[OFF_POD + d] + p] = np_src[e];
    }
}

// ============================================================
// K6: warp-per-dst-row gather over pre-scaled fp16 features.
//     Per edge: 1 uniform eidx LDG + 1 LDG.64 (fp16 row) = 3 wavefronts
// ============================================================
__global__ void gather_all() {
    int w = (blockIdx.x * blockDim.x + threadIdx.x) >> 5;
    int lane = threadIdx.x & 31;
    if (w >= OFF_TOTAL) return;

    const __half* x;
    const int* eidx;
    const int* off;
    const int* cnt;
    const float* ndst;
    float* agg;
    int local;
    if (w < NSVC) {
        local = w;
        x = g_xh + XH_SVC_OFF; eidx = g_eidx_svc; off = g_off + OFF_SVC;
        cnt = g_deg + DEG_SVC_DST; ndst = g_nrm + DEG_SVC_DST;
        agg = g_agg + AGG_SVC_OFF;
    } else if (w < NSVC + NNODE) {
        local = w - NSVC;
        x = g_xh + XH_POD_OFF; eidx = g_eidx_pn; off = g_off + OFF_NODE;
        cnt = g_deg + DEG_PN_DST; ndst = g_nrm + DEG_PN_DST;
        agg = g_agg + AGG_NODE_OFF;
    } else {
        local = w - NSVC - NNODE;
        x = g_xh + XH_NODE_OFF; eidx = g_eidx_np; off = g_off + OFF_POD;
        cnt = g_deg + DEG_NP_DST; ndst = g_nrm + DEG_NP_DST;
        agg = g_agg + AGG_POD_OFF;
    }

    int beg = off[local];
    int end = beg + cnt[local];
    const uint2* x2 = reinterpret_cast<const uint2*>(x);  // 4 halves/lane, 32/row

    float4 acc = make_float4(0.f, 0.f, 0.f, 0.f);
    int e = beg;
    for (; e + 8 <= end; e += 8) {
        int s[8];
        #pragma unroll
        for (int j = 0; j < 8; j++) s[j] = __ldg(eidx + e + j);
        uint2 u[8];
        #pragma unroll
        for (int j = 0; j < 8; j++) u[j] = x2[(size_t)s[j] * 32 + lane];
        #pragma unroll
        for (int j = 0; j < 8; j++) {
            float2 a = __half22float2(*(__half2*)&u[j].x);
            float2 b = __half22float2(*(__half2*)&u[j].y);
            acc.x += a.x; acc.y += a.y; acc.z += b.x; acc.w += b.y;
        }
    }
    if (e + 4 <= end) {
        int s[4];
        #pragma unroll
        for (int j = 0; j < 4; j++) s[j] = __ldg(eidx + e + j);
        uint2 u[4];
        #pragma unroll
        for (int j = 0; j < 4; j++) u[j] = x2[(size_t)s[j] * 32 + lane];
        #pragma unroll
        for (int j = 0; j < 4; j++) {
            float2 a = __half22float2(*(__half2*)&u[j].x);
            float2 b = __half22float2(*(__half2*)&u[j].y);
            acc.x += a.x; acc.y += a.y; acc.z += b.x; acc.w += b.y;
        }
        e += 4;
    }
    for (; e < end; e++) {
        int s0 = __ldg(eidx + e);
        uint2 u0 = x2[(size_t)s0 * 32 + lane];
        float2 a = __half22float2(*(__half2*)&u0.x);
        float2 b = __half22float2(*(__half2*)&u0.y);
        acc.x += a.x; acc.y += a.y; acc.z += b.x; acc.w += b.y;
    }
    float nd = ndst[local];
    reinterpret_cast<float4*>(agg)[(size_t)local * 32 + lane] =
        make_float4(acc.x * nd, acc.y * nd, acc.z * nd, acc.w * nd);
}

// ============================================================
// K7: fused mma.sync plain fp16 GEMM, 2 blocks/SM (R12 form)
// ============================================================
#define SROWB 272
#define SM_A    0
#define SM_W1H  34816
#define SM_W2H  69632
#define SM_B1   87040
#define SM_B2   87552
#define SM_TOTAL 87808

__device__ __forceinline__ uint32_t pack_h2(__half a, __half b) {
    return (uint32_t)__half_as_ushort(a) | ((uint32_t)__half_as_ushort(b) << 16);
}
__device__ __forceinline__ void mma_f16(float* c, uint32_t a0, uint32_t a1,
                                        uint32_t a2, uint32_t a3,
                                        uint32_t b0, uint32_t b1) {
    asm volatile(
        "mma.sync.aligned.m16n8k16.row.col.f32.f16.f16.f32 "
        "{%0,%1,%2,%3}, {%4,%5,%6,%7}, {%8,%9}, {%0,%1,%2,%3};"
        : "+f"(c[0]), "+f"(c[1]), "+f"(c[2]), "+f"(c[3])
        : "r"(a0), "r"(a1), "r"(a2), "r"(a3), "r"(b0), "r"(b1));
}
__device__ __forceinline__ uint32_t lds_u32(const char* base, int row, int col) {
    return *(const uint32_t*)(base + row * SROWB + col * 2);
}

__global__ void __launch_bounds__(256, 2)
gemm_all(const float* __restrict__ b_call, const float* __restrict__ b_lin_svc,
         const float* __restrict__ b_in,   const float* __restrict__ b_lin_node,
         const float* __restrict__ b_ni,   const float* __restrict__ b_lin_pod,
         float* __restrict__ out_base) {
    extern __shared__ char sm[];
    int tid = threadIdx.x;
    int wid = tid >> 5;
    int lane = tid & 31;
    int g = lane >> 2;
    int tig = lane & 3;

    int b = blockIdx.x;
    int t, lb, M;
    const float* agg;
    const float* b1;
    const float* b2;
    float* out;
    if (b < GB_SVC) {
        t = 0; lb = b; M = NSVC;
        agg = g_agg + AGG_SVC_OFF; b1 = b_call; b2 = b_lin_svc;
        out = out_base;
    } else if (b < GB_SVC + GB_NODE) {
        t = 1; lb = b - GB_SVC; M = NNODE;
        agg = g_agg + AGG_NODE_OFF; b1 = b_in; b2 = b_lin_node;
        out = out_base + (size_t)NSVC * OUTD;
    } else {
        t = 2; lb = b - GB_SVC - GB_NODE; M = NPOD;
        agg = g_agg + AGG_POD_OFF; b1 = b_ni; b2 = b_lin_pod;
        out = out_base + (size_t)(NSVC + NNODE) * OUTD;
    }

    // ---- stage weights ----
    {
        const uint4* s1 = (const uint4*)g_w1h[t];
        #pragma unroll
        for (int i = 0; i < 8; i++) {
            int idx = i * 256 + tid;
            int row = idx >> 4, gq = idx & 15;
            *(uint4*)(sm + SM_W1H + row * SROWB + gq * 16) = s1[idx];
        }
        const uint4* s2 = (const uint4*)g_w2h[t];
        #pragma unroll
        for (int i = 0; i < 4; i++) {
            int idx = i * 256 + tid;
            int row = idx >> 4, gq = idx & 15;
            *(uint4*)(sm + SM_W2H + row * SROWB + gq * 16) = s2[idx];
        }
    }
    if (tid < 128) ((float*)(sm + SM_B1))[tid] = b1[tid];
    else if (tid < 192) ((float*)(sm + SM_B2))[tid - 128] = b2[tid - 128];

    // ---- load A tile, convert to fp16 ----
    {
        int row = tid >> 1;
        int half = (tid & 1) * 64;
        int grow = lb * 128 + row;
        const float4* av = (const float4*)agg + (size_t)grow * 32 + (half >> 2);
        #pragma unroll
        for (int j = 0; j < 16; j++) {
            float4 v = (grow < M) ? av[j] : make_float4(0.f, 0.f, 0.f, 0.f);
            __half h0 = __float2half_rn(v.x);
            __half h1 = __float2half_rn(v.y);
            __half h2 = __float2half_rn(v.z);
            __half h3 = __float2half_rn(v.w);
            int col = half + j * 4;
            *(uint2*)(sm + SM_A + row * SROWB + col * 2) =
                make_uint2(pack_h2(h0, h1), pack_h2(h2, h3));
        }
    }
    __syncthreads();

    int mtb = (wid & 3) * 2;
    int nb1 = (wid >> 2) * 64;

    // ---- GEMM1 ----
    float acc[2][8][4];
    #pragma unroll
    for (int mt = 0; mt < 2; mt++)
        #pragma unroll
        for (int nt = 0; nt < 8; nt++)
            #pragma unroll
            for (int q = 0; q < 4; q++) acc[mt][nt][q] = 0.f;

    #pragma unroll
    for (int kc = 0; kc < 8; kc++) {
        int k0 = kc * 16 + tig * 2;
        uint32_t ah[2][4];
        #pragma unroll
        for (int mt = 0; mt < 2; mt++) {
            int r = (mtb + mt) * 16 + g;
            ah[mt][0] = lds_u32(sm + SM_A, r,     k0);
            ah[mt][1] = lds_u32(sm + SM_A, r + 8, k0);
            ah[mt][2] = lds_u32(sm + SM_A, r,     k0 + 8);
            ah[mt][3] = lds_u32(sm + SM_A, r + 8, k0 + 8);
        }
        #pragma unroll
        for (int nt = 0; nt < 8; nt++) {
            int n = nb1 + nt * 8 + g;
            uint32_t bh0 = lds_u32(sm + SM_W1H, n, k0);
            uint32_t bh1 = lds_u32(sm + SM_W1H, n, k0 + 8);
            #pragma unroll
            for (int mt = 0; mt < 2; mt++)
                mma_f16(acc[mt][nt], ah[mt][0], ah[mt][1], ah[mt][2], ah[mt][3], bh0, bh1);
        }
    }
    __syncthreads();

    // ---- epilogue1: bias + leaky -> fp16 into A ----
    {
        const float* b1s = (const float*)(sm + SM_B1);
        #pragma unroll
        for (int mt = 0; mt < 2; mt++) {
            #pragma unroll
            for (int nt = 0; nt < 8; nt++) {
                int row = (mtb + mt) * 16 + g;
                int col = nb1 + nt * 8 + tig * 2;
                float bb0 = b1s[col], bb1 = b1s[col + 1];
                float v0 = acc[mt][nt][0] + bb0;
                float v1 = acc[mt][nt][1] + bb1;
                float v2 = acc[mt][nt][2] + bb0;
                float v3 = acc[mt][nt][3] + bb1;
                v0 = v0 > 0.f ? v0 : 0.01f * v0;
                v1 = v1 > 0.f ? v1 : 0.01f * v1;
                v2 = v2 > 0.f ? v2 : 0.01f * v2;
                v3 = v3 > 0.f ? v3 : 0.01f * v3;
                *(uint32_t*)(sm + SM_A + row * SROWB + col * 2) =
                    pack_h2(__float2half_rn(v0), __float2half_rn(v1));
                *(uint32_t*)(sm + SM_A + (row + 8) * SROWB + col * 2) =
                    pack_h2(__float2half_rn(v2), __float2half_rn(v3));
            }
        }
    }
    __syncthreads();

    // ---- GEMM2 ----
    int nb2 = (wid >> 2) * 32;
    float acc2[2][4][4];
    #pragma unroll
    for (int mt = 0; mt < 2; mt++)
        #pragma unroll
        for (int nt = 0; nt < 4; nt++)
            #pragma unroll
            for (int q = 0; q < 4; q++) acc2[mt][nt][q] = 0.f;

    #pragma unroll
    for (int kc = 0; kc < 8; kc++) {
        int k0 = kc * 16 + tig * 2;
        uint32_t ah[2][4];
        #pragma unroll
        for (int mt = 0; mt < 2; mt++) {
            int r = (mtb + mt) * 16 + g;
            ah[mt][0] = lds_u32(sm + SM_A, r,     k0);
            ah[mt][1] = lds_u32(sm + SM_A, r + 8, k0);
            ah[mt][2] = lds_u32(sm + SM_A, r,     k0 + 8);
            ah[mt][3] = lds_u32(sm + SM_A, r + 8, k0 + 8);
        }
        #pragma unroll
        for (int nt = 0; nt < 4; nt++) {
            int n = nb2 + nt * 8 + g;
            uint32_t bh0 = lds_u32(sm + SM_W2H, n, k0);
            uint32_t bh1 = lds_u32(sm + SM_W2H, n, k0 + 8);
            #pragma unroll
            for (int mt = 0; mt < 2; mt++)
                mma_f16(acc2[mt][nt], ah[mt][0], ah[mt][1], ah[mt][2], ah[mt][3], bh0, bh1);
        }
    }

    // ---- epilogue2 ----
    {
        const float* b2s = (const float*)(sm + SM_B2);
        #pragma unroll
        for (int mt = 0; mt < 2; mt++) {
            #pragma unroll
            for (int nt = 0; nt < 4; nt++) {
                int row = lb * 128 + (mtb + mt) * 16 + g;
                int col = nb2 + nt * 8 + tig * 2;
                float bb0 = b2s[col], bb1 = b2s[col + 1];
                if (row < M)
                    *(float2*)(out + (size_t)row * 64 + col) =
                        make_float2(acc2[mt][nt][0] + bb0, acc2[mt][nt][1] + bb1);
                if (row + 8 < M)
                    *(float2*)(out + (size_t)(row + 8) * 64 + col) =
                        make_float2(acc2[mt][nt][2] + bb0, acc2[mt][nt][3] + bb1);
            }
        }
    }
}

// ============================================================
// launch — 7 kernels total
// ============================================================
extern "C" void kernel_launch(void* const* d_in, const int* in_sizes, int n_in,
                              void* d_out, int out_size) {
    const float* x_svc  = (const float*)d_in[0];
    const float* x_pod  = (const float*)d_in[1];
    const float* x_node = (const float*)d_in[2];
    const int* svc_src = (const int*)d_in[3];
    const int* svc_dst = (const int*)d_in[4];
    const int* pn_src  = (const int*)d_in[5];
    const int* pn_dst  = (const int*)d_in[6];
    const int* np_src  = (const int*)d_in[7];
    const int* np_dst  = (const int*)d_in[8];
    const float* W_call = (const float*)d_in[9];
    const float* b_call = (const float*)d_in[10];
    const float* W_in   = (const float*)d_in[11];
    const float* b_in   = (const float*)d_in[12];
    const float* W_ni   = (const float*)d_in[13];
    const float* b_ni   = (const float*)d_in[14];
    const float* W_lin_svc  = (const float*)d_in[15];
    const float* b_lin_svc  = (const float*)d_in[16];
    const float* W_lin_node = (const float*)d_in[17];
    const float* b_lin_node = (const float*)d_in[18];
    const float* W_lin_pod  = (const float*)d_in[19];
    const float* b_lin_pod  = (const float*)d_in[20];
    float* out = (float*)d_out;

    int E_svc = in_sizes[3];
    int E_pn  = in_sizes[5];
    int E_np  = in_sizes[7];
    int E_tot = E_svc + E_pn + E_np;

    cudaFuncSetAttribute(gemm_all, cudaFuncAttributeMaxDynamicSharedMemorySize, SM_TOTAL);

    prep0<<<512, 256>>>(W_call, W_lin_svc, W_in, W_lin_node, W_ni, W_lin_pod);

    deg_all<<<(E_tot + 255) / 256, 256>>>(svc_src, svc_dst, pn_src, pn_dst,
                                          np_src, np_dst, E_svc, E_pn, E_np);

    scan1_all<<<NB_ALL, 1024>>>();
    scan23x<<<NB_ALL + XS_BLOCKS, 1024>>>(x_svc, x_pod, x_node);

    fill_all<<<(E_tot + 255) / 256, 256>>>(svc_src, svc_dst, pn_src, pn_dst,
                                           np_src, np_dst, E_svc, E_pn, E_np);

    gather_all<<<(OFF_TOTAL + 7) / 8, 256>>>();

    gemm_all<<<GB_ALL, 256, SM_TOTAL>>>(b_call, b_lin_svc, b_in, b_lin_node,
                                        b_ni, b_lin_pod, out);
}